// round 1
// baseline (speedup 1.0000x reference)
#include <cuda_runtime.h>

// ---------------------------------------------------------------------------
// Problem constants: B=4, T=2048, C=1024, H=16, D=64
//   qkv   = x @ Wqkv          [8192, 3072]
//   q,k,v -> [B,H,T,D]
//   att   = softmax(causal(q k^T / 8)) v      -> attOut [B,T,C]
//   out   = attOut @ Wproj    [8192, 1024]
// ---------------------------------------------------------------------------

#define NBH   (4 * 16)          // B*H = 64
#define NT    2048
#define ND    64
#define NC    1024
#define NM    8192              // B*T

__device__ float g_q[NBH * NT * ND];
__device__ float g_k[NBH * NT * ND];
__device__ float g_v[NBH * NT * ND];
__device__ float g_att[NM * NC];

// ---------------------------------------------------------------------------
// SGEMM: 128x128 block tile, BK=8, 256 threads, 8x8 per-thread register tile.
// MODE 0: plain C store.  MODE 1: QKV scatter store.  MODE 2: A = g_att.
// M,N,K all multiples of 128/8 -> no bounds checks.
// ---------------------------------------------------------------------------
template <int MODE>
__global__ void __launch_bounds__(256) sgemm_kernel(
    const float* __restrict__ A, const float* __restrict__ B,
    float* __restrict__ C, int M, int N, int K)
{
    __shared__ float As[8][128];   // transposed A tile: As[k][m]
    __shared__ float Bs[8][128];

    const int tid = threadIdx.x;
    const int tx  = tid & 15;      // 0..15 -> N
    const int ty  = tid >> 4;      // 0..15 -> M
    const int bm  = blockIdx.y << 7;
    const int bn  = blockIdx.x << 7;

    const float* Ab = (MODE == 2) ? (const float*)g_att : A;

    // A tile load: 128 rows x 8 k, float4 along K
    const int arow = tid >> 1;            // 0..127
    const int acol = (tid & 1) << 2;      // 0 or 4
    // B tile load: 8 rows x 128 n, float4 along N
    const int brow = tid >> 5;            // 0..7
    const int bcol = (tid & 31) << 2;     // 0..124

    const float* Ap = Ab + (size_t)(bm + arow) * K + acol;
    const float* Bp = B  + (size_t)brow * N + bn + bcol;

    float acc[8][8];
#pragma unroll
    for (int i = 0; i < 8; i++)
#pragma unroll
        for (int j = 0; j < 8; j++) acc[i][j] = 0.0f;

    for (int k0 = 0; k0 < K; k0 += 8) {
        float4 av = *(const float4*)Ap;  Ap += 8;
        float4 bv = *(const float4*)Bp;  Bp += (size_t)8 * N;

        __syncthreads();
        As[acol + 0][arow] = av.x;
        As[acol + 1][arow] = av.y;
        As[acol + 2][arow] = av.z;
        As[acol + 3][arow] = av.w;
        *(float4*)&Bs[brow][bcol] = bv;
        __syncthreads();

#pragma unroll
        for (int kk = 0; kk < 8; kk++) {
            float4 a0 = *(const float4*)&As[kk][ty << 3];
            float4 a1 = *(const float4*)&As[kk][(ty << 3) + 4];
            float4 b0 = *(const float4*)&Bs[kk][tx << 3];
            float4 b1 = *(const float4*)&Bs[kk][(tx << 3) + 4];
            float ra[8] = {a0.x, a0.y, a0.z, a0.w, a1.x, a1.y, a1.z, a1.w};
            float rb[8] = {b0.x, b0.y, b0.z, b0.w, b1.x, b1.y, b1.z, b1.w};
#pragma unroll
            for (int i = 0; i < 8; i++)
#pragma unroll
                for (int j = 0; j < 8; j++)
                    acc[i][j] = fmaf(ra[i], rb[j], acc[i][j]);
        }
    }

    if (MODE == 1) {
        // scatter qkv columns into g_q/g_k/g_v as [B,H,T,D]
        const int gc    = bn + (tx << 3);       // global col, multiple of 8
        const int which = gc >> 10;             // 0=q 1=k 2=v
        const int h     = (gc & 1023) >> 6;
        const int d0    = gc & 63;
        float* dst = (which == 0) ? g_q : (which == 1) ? g_k : g_v;
#pragma unroll
        for (int i = 0; i < 8; i++) {
            const int gr = bm + (ty << 3) + i;  // global row = b*T + t
            const int b  = gr >> 11;
            const int t  = gr & 2047;
            float* p = dst + ((size_t)((b * 16 + h) * 2048 + t) << 6) + d0;
            *(float4*)(p)     = make_float4(acc[i][0], acc[i][1], acc[i][2], acc[i][3]);
            *(float4*)(p + 4) = make_float4(acc[i][4], acc[i][5], acc[i][6], acc[i][7]);
        }
    } else {
#pragma unroll
        for (int i = 0; i < 8; i++) {
            float* p = C + (size_t)(bm + (ty << 3) + i) * N + bn + (tx << 3);
            *(float4*)(p)     = make_float4(acc[i][0], acc[i][1], acc[i][2], acc[i][3]);
            *(float4*)(p + 4) = make_float4(acc[i][4], acc[i][5], acc[i][6], acc[i][7]);
        }
    }
}

// ---------------------------------------------------------------------------
// Causal flash attention: one block per (bh, 64-row q tile).
// 256 threads as 16x16, 4x4 S-tile and 4x4 O-tile per thread.
// smem: Qt[64][68] (d-major), KP[64][68] (K tile d-major, reused as P), Vs[64][68].
// Online softmax, fp32.
// ---------------------------------------------------------------------------
#define SROW 68   // padded row length (68*4B = 272B, 16B-aligned rows)

__global__ void __launch_bounds__(256) attn_kernel()
{
    extern __shared__ float sm[];
    float* Qt = sm;                    // [64][SROW]  Qt[d][r]
    float* KP = sm + 64 * SROW;        // [64][SROW]  Kt[d][c]  then  P[r][c]
    float* Vs = sm + 2 * 64 * SROW;    // [64][SROW]  Vs[k][c]

    const int tid = threadIdx.x;
    const int tx  = tid & 15;
    const int ty  = tid >> 4;
    const int bh  = blockIdx.y;
    const int q0  = blockIdx.x << 6;

    const float* Qg  = g_q + ((size_t)bh * NT + q0) * ND;
    const float* Kg0 = g_k + (size_t)bh * NT * ND;
    const float* Vg0 = g_v + (size_t)bh * NT * ND;

    // load Q transposed into Qt[d][r]
#pragma unroll
    for (int i = 0; i < 4; i++) {
        int idx = tid + (i << 8);
        int d   = idx & 63;
        int r4  = (idx >> 6) << 2;
        float4 v;
        v.x = Qg[(r4 + 0) * 64 + d];
        v.y = Qg[(r4 + 1) * 64 + d];
        v.z = Qg[(r4 + 2) * 64 + d];
        v.w = Qg[(r4 + 3) * 64 + d];
        *(float4*)&Qt[d * SROW + r4] = v;
    }

    float m[4], l[4], o[4][4];
#pragma unroll
    for (int i = 0; i < 4; i++) {
        m[i] = -1e30f;
        l[i] = 0.0f;
#pragma unroll
        for (int j = 0; j < 4; j++) o[i][j] = 0.0f;
    }

    const int ktmax = q0 >> 6;
    for (int kt = 0; kt <= ktmax; kt++) {
        const float* Kg = Kg0 + ((size_t)kt << 12);
        const float* Vg = Vg0 + ((size_t)kt << 12);

        __syncthreads();   // prior PV reads of KP/Vs complete
        // K tile transposed into KP[d][c]
#pragma unroll
        for (int i = 0; i < 4; i++) {
            int idx = tid + (i << 8);
            int d   = idx & 63;
            int r4  = (idx >> 6) << 2;
            float4 v;
            v.x = Kg[(r4 + 0) * 64 + d];
            v.y = Kg[(r4 + 1) * 64 + d];
            v.z = Kg[(r4 + 2) * 64 + d];
            v.w = Kg[(r4 + 3) * 64 + d];
            *(float4*)&KP[d * SROW + r4] = v;
        }
        // V tile direct: Vs[k][c]
#pragma unroll
        for (int i = 0; i < 4; i++) {
            int idx = tid + (i << 8);
            int r   = idx >> 4;
            int d4  = (idx & 15) << 2;
            *(float4*)&Vs[r * SROW + d4] = *(const float4*)(Vg + r * 64 + d4);
        }
        __syncthreads();

        // S = Q K^T  (4x4 per thread)
        float acc[4][4];
#pragma unroll
        for (int i = 0; i < 4; i++)
#pragma unroll
            for (int j = 0; j < 4; j++) acc[i][j] = 0.0f;

#pragma unroll 16
        for (int d = 0; d < 64; d++) {
            float4 qa = *(const float4*)&Qt[d * SROW + (ty << 2)];
            float4 kb = *(const float4*)&KP[d * SROW + (tx << 2)];
            float qr[4] = {qa.x, qa.y, qa.z, qa.w};
            float kc[4] = {kb.x, kb.y, kb.z, kb.w};
#pragma unroll
            for (int i = 0; i < 4; i++)
#pragma unroll
                for (int j = 0; j < 4; j++)
                    acc[i][j] = fmaf(qr[i], kc[j], acc[i][j]);
        }

        // scale + causal mask (only the diagonal tile needs masking)
        if (kt == ktmax) {
#pragma unroll
            for (int i = 0; i < 4; i++)
#pragma unroll
                for (int j = 0; j < 4; j++) {
                    bool ok = ((tx << 2) + j) <= ((ty << 2) + i);
                    acc[i][j] = ok ? acc[i][j] * 0.125f : -1e30f;
                }
        } else {
#pragma unroll
            for (int i = 0; i < 4; i++)
#pragma unroll
                for (int j = 0; j < 4; j++) acc[i][j] *= 0.125f;
        }

        // online softmax (row reductions across the 16 tx lanes via shfl)
#pragma unroll
        for (int i = 0; i < 4; i++) {
            float rm = fmaxf(fmaxf(acc[i][0], acc[i][1]),
                             fmaxf(acc[i][2], acc[i][3]));
#pragma unroll
            for (int off = 8; off > 0; off >>= 1)
                rm = fmaxf(rm, __shfl_xor_sync(0xffffffffu, rm, off));
            float mnew = fmaxf(m[i], rm);
            float sc   = __expf(m[i] - mnew);
            float rs   = 0.0f;
#pragma unroll
            for (int j = 0; j < 4; j++) {
                acc[i][j] = __expf(acc[i][j] - mnew);
                rs += acc[i][j];
            }
#pragma unroll
            for (int off = 8; off > 0; off >>= 1)
                rs += __shfl_xor_sync(0xffffffffu, rs, off);
            l[i] = l[i] * sc + rs;
            m[i] = mnew;
#pragma unroll
            for (int j = 0; j < 4; j++) o[i][j] *= sc;
        }

        __syncthreads();   // all S reads of KP done -> safe to overwrite with P
#pragma unroll
        for (int i = 0; i < 4; i++)
            *(float4*)&KP[((ty << 2) + i) * SROW + (tx << 2)] =
                make_float4(acc[i][0], acc[i][1], acc[i][2], acc[i][3]);
        __syncthreads();

        // O += P V
#pragma unroll 8
        for (int k = 0; k < 64; k++) {
            float4 vb = *(const float4*)&Vs[k * SROW + (tx << 2)];
#pragma unroll
            for (int i = 0; i < 4; i++) {
                float p = KP[((ty << 2) + i) * SROW + k];
                o[i][0] = fmaf(p, vb.x, o[i][0]);
                o[i][1] = fmaf(p, vb.y, o[i][1]);
                o[i][2] = fmaf(p, vb.z, o[i][2]);
                o[i][3] = fmaf(p, vb.w, o[i][3]);
            }
        }
    }

    // epilogue: attOut[b][t][h*64 + d]
    const int b = bh >> 4;
    const int h = bh & 15;
    float* Og = g_att + ((size_t)b * NT + q0) * NC + (h << 6);
#pragma unroll
    for (int i = 0; i < 4; i++) {
        float inv = 1.0f / l[i];
        float4 r = make_float4(o[i][0] * inv, o[i][1] * inv,
                               o[i][2] * inv, o[i][3] * inv);
        *(float4*)(Og + (size_t)((ty << 2) + i) * NC + (tx << 2)) = r;
    }
}

// ---------------------------------------------------------------------------
// launch
// ---------------------------------------------------------------------------
extern "C" void kernel_launch(void* const* d_in, const int* in_sizes, int n_in,
                              void* d_out, int out_size)
{
    const float* x     = (const float*)d_in[0];
    const float* Wqkv  = (const float*)d_in[1];
    const float* Wproj = (const float*)d_in[2];
    float* out = (float*)d_out;

    const int attn_smem = 3 * 64 * SROW * (int)sizeof(float);  // 52224 B
    cudaFuncSetAttribute(attn_kernel,
                         cudaFuncAttributeMaxDynamicSharedMemorySize, attn_smem);

    // 1) qkv = x @ Wqkv, scattered into g_q/g_k/g_v [B,H,T,D]
    sgemm_kernel<1><<<dim3(3072 / 128, 8192 / 128), 256>>>(
        x, Wqkv, nullptr, NM, 3 * NC, NC);

    // 2) causal attention -> g_att [B,T,C]
    attn_kernel<<<dim3(NT / 64, NBH), 256, attn_smem>>>();

    // 3) out = g_att @ Wproj
    sgemm_kernel<2><<<dim3(1024 / 128, 8192 / 128), 256>>>(
        nullptr, Wproj, out, NM, NC, NC);
}

// round 2
// speedup vs baseline: 2.4251x; 2.4251x over previous
#include <cuda_runtime.h>

// ---------------------------------------------------------------------------
// B=4, T=2048, C=1024, H=16, D=64
//   qkv = x @ Wqkv  -> scatter q,k,v [B,H,T,D]
//   att = softmax(causal(qk^T/8)) v -> g_att [B,T,C]
//   out = g_att @ Wproj
// All matmuls on tensor cores: mma.sync.m16n8k8 tf32 (RN-rounded inputs).
// ---------------------------------------------------------------------------

#define NBH 64
#define NT  2048
#define ND  64
#define NC  1024
#define NM  8192

__device__ float g_q[NBH * NT * ND];
__device__ float g_k[NBH * NT * ND];
__device__ float g_v[NBH * NT * ND];
__device__ float g_att[NM * NC];

__device__ __forceinline__ unsigned f2tf(float f) {
    unsigned u;
    asm("cvt.rna.tf32.f32 %0, %1;" : "=r"(u) : "f"(f));
    return u;
}

__device__ __forceinline__ void mma_tf32(float* c, const unsigned* a,
                                         unsigned b0, unsigned b1) {
    asm volatile(
        "mma.sync.aligned.m16n8k8.row.col.f32.tf32.tf32.f32 "
        "{%0,%1,%2,%3}, {%4,%5,%6,%7}, {%8,%9}, {%0,%1,%2,%3};"
        : "+f"(c[0]), "+f"(c[1]), "+f"(c[2]), "+f"(c[3])
        : "r"(a[0]), "r"(a[1]), "r"(a[2]), "r"(a[3]), "r"(b0), "r"(b1));
}

// ---------------------------------------------------------------------------
// tf32 GEMM: block 128m x 256n, BK=16, 256 threads (8 warps, 2x4, 64x64/warp)
// smem: As[k][m] stride 136 (k-major, transposed), Bs[k][n] stride 264.
// Both strides ≡ 8 (mod 32) -> conflict-free fragment LDS.
// MODE 0: plain store. MODE 1: QKV scatter. MODE 2: A = g_att.
// ---------------------------------------------------------------------------
#define AS_STRIDE 136
#define BS_STRIDE 264
#define ASTAGE (16 * AS_STRIDE)
#define BSTAGE (16 * BS_STRIDE)
#define GEMM_SMEM ((2 * (ASTAGE + BSTAGE)) * 4)

template <int MODE>
__global__ void __launch_bounds__(256, 1) gemm_tc(
    const float* __restrict__ A, const float* __restrict__ Bm,
    float* __restrict__ Cm, int M, int N, int K)
{
    extern __shared__ unsigned sh[];
    unsigned* As = sh;                 // [2][16][AS_STRIDE]
    unsigned* Bs = sh + 2 * ASTAGE;    // [2][16][BS_STRIDE]

    const int tid  = threadIdx.x;
    const int lane = tid & 31;
    const int w    = tid >> 5;
    const int wm   = w >> 2;          // 0..1
    const int wn   = w & 3;           // 0..3
    const int g    = lane >> 2;       // 0..7
    const int cq   = lane & 3;        // 0..3
    const int bm   = blockIdx.y << 7;
    const int bn   = blockIdx.x << 8;

    const float* Ab = (MODE == 2) ? (const float*)g_att : A;

    // gmem load assignments
    const int am  = tid & 127;        // A row
    const int ak  = (tid >> 7) * 4;   // A k base (covers ak..ak+3, ak+8..ak+11)
    const int bk  = tid >> 4;         // B row (0..15)
    const int bn4 = (tid & 15) * 4;   // B col base (+ j*64)

    const float* Ap = Ab + (size_t)(bm + am) * K + ak;
    const float* Bp = Bm + (size_t)bk * N + bn + bn4;

    float acc[4][8][4];
#pragma unroll
    for (int mi = 0; mi < 4; mi++)
#pragma unroll
        for (int ni = 0; ni < 8; ni++)
#pragma unroll
            for (int r = 0; r < 4; r++) acc[mi][ni][r] = 0.0f;

    float4 la0, la1, lb0, lb1, lb2, lb3;

    // prologue: tile 0
    la0 = *(const float4*)(Ap);
    la1 = *(const float4*)(Ap + 8);
    lb0 = *(const float4*)(Bp);
    lb1 = *(const float4*)(Bp + 64);
    lb2 = *(const float4*)(Bp + 128);
    lb3 = *(const float4*)(Bp + 192);

    {
        unsigned* Asb = As;
        unsigned* Bsb = Bs;
        Asb[(ak + 0) * AS_STRIDE + am] = f2tf(la0.x);
        Asb[(ak + 1) * AS_STRIDE + am] = f2tf(la0.y);
        Asb[(ak + 2) * AS_STRIDE + am] = f2tf(la0.z);
        Asb[(ak + 3) * AS_STRIDE + am] = f2tf(la0.w);
        Asb[(ak + 8) * AS_STRIDE + am] = f2tf(la1.x);
        Asb[(ak + 9) * AS_STRIDE + am] = f2tf(la1.y);
        Asb[(ak + 10) * AS_STRIDE + am] = f2tf(la1.z);
        Asb[(ak + 11) * AS_STRIDE + am] = f2tf(la1.w);
        uint4 u;
        u.x = f2tf(lb0.x); u.y = f2tf(lb0.y); u.z = f2tf(lb0.z); u.w = f2tf(lb0.w);
        *(uint4*)&Bsb[bk * BS_STRIDE + bn4] = u;
        u.x = f2tf(lb1.x); u.y = f2tf(lb1.y); u.z = f2tf(lb1.z); u.w = f2tf(lb1.w);
        *(uint4*)&Bsb[bk * BS_STRIDE + bn4 + 64] = u;
        u.x = f2tf(lb2.x); u.y = f2tf(lb2.y); u.z = f2tf(lb2.z); u.w = f2tf(lb2.w);
        *(uint4*)&Bsb[bk * BS_STRIDE + bn4 + 128] = u;
        u.x = f2tf(lb3.x); u.y = f2tf(lb3.y); u.z = f2tf(lb3.z); u.w = f2tf(lb3.w);
        *(uint4*)&Bsb[bk * BS_STRIDE + bn4 + 192] = u;
    }

    const int NIT = K >> 4;
#pragma unroll 1
    for (int kt = 0; kt < NIT; kt++) {
        if (kt + 1 < NIT) {
            const float* Ap2 = Ap + (kt + 1) * 16;
            const float* Bp2 = Bp + (size_t)(kt + 1) * 16 * N;
            la0 = *(const float4*)(Ap2);
            la1 = *(const float4*)(Ap2 + 8);
            lb0 = *(const float4*)(Bp2);
            lb1 = *(const float4*)(Bp2 + 64);
            lb2 = *(const float4*)(Bp2 + 128);
            lb3 = *(const float4*)(Bp2 + 192);
        }
        __syncthreads();

        const unsigned* Asb = As + (kt & 1) * ASTAGE;
        const unsigned* Bsb = Bs + (kt & 1) * BSTAGE;

#pragma unroll
        for (int ks = 0; ks < 2; ks++) {
            unsigned af[4][4], bf[8][2];
#pragma unroll
            for (int mi = 0; mi < 4; mi++) {
                const int row = wm * 64 + mi * 16 + g;
                const unsigned* pa = Asb + (ks * 8 + cq) * AS_STRIDE;
                af[mi][0] = pa[row];
                af[mi][1] = pa[row + 8];
                af[mi][2] = pa[4 * AS_STRIDE + row];
                af[mi][3] = pa[4 * AS_STRIDE + row + 8];
            }
#pragma unroll
            for (int ni = 0; ni < 8; ni++) {
                const int col = wn * 64 + ni * 8 + g;
                const unsigned* pb = Bsb + (ks * 8 + cq) * BS_STRIDE + col;
                bf[ni][0] = pb[0];
                bf[ni][1] = pb[4 * BS_STRIDE];
            }
#pragma unroll
            for (int mi = 0; mi < 4; mi++)
#pragma unroll
                for (int ni = 0; ni < 8; ni++)
                    mma_tf32(acc[mi][ni], af[mi], bf[ni][0], bf[ni][1]);
        }

        if (kt + 1 < NIT) {
            unsigned* Asb2 = As + ((kt + 1) & 1) * ASTAGE;
            unsigned* Bsb2 = Bs + ((kt + 1) & 1) * BSTAGE;
            Asb2[(ak + 0) * AS_STRIDE + am] = f2tf(la0.x);
            Asb2[(ak + 1) * AS_STRIDE + am] = f2tf(la0.y);
            Asb2[(ak + 2) * AS_STRIDE + am] = f2tf(la0.z);
            Asb2[(ak + 3) * AS_STRIDE + am] = f2tf(la0.w);
            Asb2[(ak + 8) * AS_STRIDE + am] = f2tf(la1.x);
            Asb2[(ak + 9) * AS_STRIDE + am] = f2tf(la1.y);
            Asb2[(ak + 10) * AS_STRIDE + am] = f2tf(la1.z);
            Asb2[(ak + 11) * AS_STRIDE + am] = f2tf(la1.w);
            uint4 u;
            u.x = f2tf(lb0.x); u.y = f2tf(lb0.y); u.z = f2tf(lb0.z); u.w = f2tf(lb0.w);
            *(uint4*)&Bsb2[bk * BS_STRIDE + bn4] = u;
            u.x = f2tf(lb1.x); u.y = f2tf(lb1.y); u.z = f2tf(lb1.z); u.w = f2tf(lb1.w);
            *(uint4*)&Bsb2[bk * BS_STRIDE + bn4 + 64] = u;
            u.x = f2tf(lb2.x); u.y = f2tf(lb2.y); u.z = f2tf(lb2.z); u.w = f2tf(lb2.w);
            *(uint4*)&Bsb2[bk * BS_STRIDE + bn4 + 128] = u;
            u.x = f2tf(lb3.x); u.y = f2tf(lb3.y); u.z = f2tf(lb3.z); u.w = f2tf(lb3.w);
            *(uint4*)&Bsb2[bk * BS_STRIDE + bn4 + 192] = u;
        }
    }

    // epilogue
#pragma unroll
    for (int mi = 0; mi < 4; mi++) {
        const int row = bm + wm * 64 + mi * 16 + g;
#pragma unroll
        for (int ni = 0; ni < 8; ni++) {
            const int col = bn + wn * 64 + ni * 8 + 2 * cq;
            if (MODE == 1) {
                const int which = col >> 10;            // 0=q 1=k 2=v
                const int h     = (col & 1023) >> 6;
                const int d0    = col & 63;
                float* dst = (which == 0) ? g_q : (which == 1) ? g_k : g_v;
                {
                    const int b = row >> 11, t = row & 2047;
                    float* p = dst + ((size_t)((b * 16 + h) * 2048 + t) << 6) + d0;
                    *(float2*)p = make_float2(acc[mi][ni][0], acc[mi][ni][1]);
                }
                {
                    const int r2 = row + 8;
                    const int b = r2 >> 11, t = r2 & 2047;
                    float* p = dst + ((size_t)((b * 16 + h) * 2048 + t) << 6) + d0;
                    *(float2*)p = make_float2(acc[mi][ni][2], acc[mi][ni][3]);
                }
            } else {
                *(float2*)&Cm[(size_t)row * N + col] =
                    make_float2(acc[mi][ni][0], acc[mi][ni][1]);
                *(float2*)&Cm[(size_t)(row + 8) * N + col] =
                    make_float2(acc[mi][ni][2], acc[mi][ni][3]);
            }
        }
    }
}

// ---------------------------------------------------------------------------
// Causal flash attention, tf32 tensor cores.
// Block: (bh, 64-q-row tile), 128 threads = 4 warps.
// Warp w owns q rows [w*16, w*16+16) and full 64-col k tile:
//   S mma: 8 n-tiles x 8 k-steps; softmax intra-warp; P -> smem (warp-private
//   rows, __syncwarp only); PV mma: 8 n-tiles(d) x 8 k-steps.
// smem arrays stride 72 (≡8 mod 32): conflict-free fragment LDS.
// ---------------------------------------------------------------------------
#define ATS 72
#define ATTN_SMEM (4 * 64 * ATS * 4)

__global__ void __launch_bounds__(128, 1) attn_tc()
{
    extern __shared__ unsigned sh[];
    unsigned* Qs = sh;                 // [64][ATS] q rows x d
    unsigned* Ks = sh + 64 * ATS;      // [64][ATS] k rows x d
    unsigned* Vs = sh + 2 * 64 * ATS;  // [64][ATS] k rows x d
    unsigned* Ps = sh + 3 * 64 * ATS;  // [64][ATS] q rows x kpos

    const int tid  = threadIdx.x;
    const int lane = tid & 31;
    const int w    = tid >> 5;
    const int g    = lane >> 2;
    const int cq   = lane & 3;
    const int bh   = blockIdx.y;
    const int q0   = blockIdx.x << 6;

    const float* Qg  = g_q + ((size_t)bh * NT + q0) * ND;
    const float* Kg0 = g_k + (size_t)bh * NT * ND;
    const float* Vg0 = g_v + (size_t)bh * NT * ND;

    // load Q (cvt to tf32)
#pragma unroll
    for (int i = 0; i < 8; i++) {
        int idx = i * 128 + tid;
        int r = idx >> 4, c4 = (idx & 15) << 2;
        float4 v = *(const float4*)(Qg + r * 64 + c4);
        uint4 u;
        u.x = f2tf(v.x); u.y = f2tf(v.y); u.z = f2tf(v.z); u.w = f2tf(v.w);
        *(uint4*)&Qs[r * ATS + c4] = u;
    }

    float m0 = -1e30f, m1 = -1e30f, l0 = 0.0f, l1 = 0.0f;
    float o[8][4];
#pragma unroll
    for (int nt = 0; nt < 8; nt++)
#pragma unroll
        for (int r = 0; r < 4; r++) o[nt][r] = 0.0f;

    const int rq  = w * 16 + g;   // local q row (thread's row0)
    const int ktmax = q0 >> 6;

    for (int kt = 0; kt <= ktmax; kt++) {
        const float* Kg = Kg0 + ((size_t)kt << 12);
        const float* Vg = Vg0 + ((size_t)kt << 12);

        __syncthreads();  // prior iter's reads of Ks/Vs done
#pragma unroll
        for (int i = 0; i < 8; i++) {
            int idx = i * 128 + tid;
            int r = idx >> 4, c4 = (idx & 15) << 2;
            float4 v = *(const float4*)(Kg + r * 64 + c4);
            uint4 u;
            u.x = f2tf(v.x); u.y = f2tf(v.y); u.z = f2tf(v.z); u.w = f2tf(v.w);
            *(uint4*)&Ks[r * ATS + c4] = u;
            float4 vv = *(const float4*)(Vg + r * 64 + c4);
            u.x = f2tf(vv.x); u.y = f2tf(vv.y); u.z = f2tf(vv.z); u.w = f2tf(vv.w);
            *(uint4*)&Vs[r * ATS + c4] = u;
        }
        __syncthreads();

        // S = Q K^T
        float s[8][4];
#pragma unroll
        for (int nt = 0; nt < 8; nt++)
#pragma unroll
            for (int r = 0; r < 4; r++) s[nt][r] = 0.0f;

#pragma unroll
        for (int ks = 0; ks < 8; ks++) {
            unsigned af[4];
            const unsigned* pq = Qs + ks * 8 + cq;
            af[0] = pq[rq * ATS];
            af[1] = pq[(rq + 8) * ATS];
            af[2] = pq[rq * ATS + 4];
            af[3] = pq[(rq + 8) * ATS + 4];
#pragma unroll
            for (int nt = 0; nt < 8; nt++) {
                const unsigned* pk = Ks + (nt * 8 + g) * ATS + ks * 8 + cq;
                mma_tf32(s[nt], af, pk[0], pk[4]);
            }
        }

        // scale + causal mask (diag tile only)
#pragma unroll
        for (int nt = 0; nt < 8; nt++)
#pragma unroll
            for (int r = 0; r < 4; r++) s[nt][r] *= 0.125f;
        if (kt == ktmax) {
#pragma unroll
            for (int nt = 0; nt < 8; nt++) {
                int col = nt * 8 + 2 * cq;
                if (col     > rq)     s[nt][0] = -1e30f;
                if (col + 1 > rq)     s[nt][1] = -1e30f;
                if (col     > rq + 8) s[nt][2] = -1e30f;
                if (col + 1 > rq + 8) s[nt][3] = -1e30f;
            }
        }

        // online softmax (rows rq, rq+8); reduce over lanes sharing g
        float rm0 = -1e30f, rm1 = -1e30f;
#pragma unroll
        for (int nt = 0; nt < 8; nt++) {
            rm0 = fmaxf(rm0, fmaxf(s[nt][0], s[nt][1]));
            rm1 = fmaxf(rm1, fmaxf(s[nt][2], s[nt][3]));
        }
        rm0 = fmaxf(rm0, __shfl_xor_sync(0xffffffffu, rm0, 1));
        rm0 = fmaxf(rm0, __shfl_xor_sync(0xffffffffu, rm0, 2));
        rm1 = fmaxf(rm1, __shfl_xor_sync(0xffffffffu, rm1, 1));
        rm1 = fmaxf(rm1, __shfl_xor_sync(0xffffffffu, rm1, 2));

        float mn0 = fmaxf(m0, rm0), mn1 = fmaxf(m1, rm1);
        float sc0 = __expf(m0 - mn0), sc1 = __expf(m1 - mn1);
        float rs0 = 0.0f, rs1 = 0.0f;
#pragma unroll
        for (int nt = 0; nt < 8; nt++) {
            s[nt][0] = __expf(s[nt][0] - mn0);
            s[nt][1] = __expf(s[nt][1] - mn0);
            s[nt][2] = __expf(s[nt][2] - mn1);
            s[nt][3] = __expf(s[nt][3] - mn1);
            rs0 += s[nt][0] + s[nt][1];
            rs1 += s[nt][2] + s[nt][3];
        }
        rs0 += __shfl_xor_sync(0xffffffffu, rs0, 1);
        rs0 += __shfl_xor_sync(0xffffffffu, rs0, 2);
        rs1 += __shfl_xor_sync(0xffffffffu, rs1, 1);
        rs1 += __shfl_xor_sync(0xffffffffu, rs1, 2);
        l0 = l0 * sc0 + rs0;
        l1 = l1 * sc1 + rs1;
        m0 = mn0; m1 = mn1;
#pragma unroll
        for (int nt = 0; nt < 8; nt++) {
            o[nt][0] *= sc0; o[nt][1] *= sc0;
            o[nt][2] *= sc1; o[nt][3] *= sc1;
        }

        // P -> smem (warp-private rows), cvt to tf32
#pragma unroll
        for (int nt = 0; nt < 8; nt++) {
            uint2 u0, u1;
            u0.x = f2tf(s[nt][0]); u0.y = f2tf(s[nt][1]);
            u1.x = f2tf(s[nt][2]); u1.y = f2tf(s[nt][3]);
            *(uint2*)&Ps[rq * ATS + nt * 8 + 2 * cq] = u0;
            *(uint2*)&Ps[(rq + 8) * ATS + nt * 8 + 2 * cq] = u1;
        }
        __syncwarp();

        // O += P V
#pragma unroll
        for (int ks = 0; ks < 8; ks++) {
            unsigned af[4];
            const unsigned* pp = Ps + ks * 8 + cq;
            af[0] = pp[rq * ATS];
            af[1] = pp[(rq + 8) * ATS];
            af[2] = pp[rq * ATS + 4];
            af[3] = pp[(rq + 8) * ATS + 4];
#pragma unroll
            for (int nt = 0; nt < 8; nt++) {
                const unsigned* pv = Vs + (ks * 8 + cq) * ATS + nt * 8 + g;
                mma_tf32(o[nt], af, pv[0], pv[4 * ATS]);
            }
        }
        __syncwarp();   // keep Ps reads inside this iter before next overwrite
    }

    // epilogue: attOut[b][t][h*64 + d], divide by l
    const int b = bh >> 4;
    const int h = bh & 15;
    const float inv0 = 1.0f / l0;
    const float inv1 = 1.0f / l1;
    float* Og = g_att + ((size_t)(b * NT + q0 + rq)) * NC + (h << 6);
#pragma unroll
    for (int nt = 0; nt < 8; nt++) {
        int col = nt * 8 + 2 * cq;
        *(float2*)(Og + col) = make_float2(o[nt][0] * inv0, o[nt][1] * inv0);
        *(float2*)(Og + (size_t)8 * NC + col) =
            make_float2(o[nt][2] * inv1, o[nt][3] * inv1);
    }
}

// ---------------------------------------------------------------------------
// launch
// ---------------------------------------------------------------------------
extern "C" void kernel_launch(void* const* d_in, const int* in_sizes, int n_in,
                              void* d_out, int out_size)
{
    const float* x     = (const float*)d_in[0];
    const float* Wqkv  = (const float*)d_in[1];
    const float* Wproj = (const float*)d_in[2];
    float* out = (float*)d_out;

    cudaFuncSetAttribute(gemm_tc<1>,
                         cudaFuncAttributeMaxDynamicSharedMemorySize, GEMM_SMEM);
    cudaFuncSetAttribute(gemm_tc<2>,
                         cudaFuncAttributeMaxDynamicSharedMemorySize, GEMM_SMEM);
    cudaFuncSetAttribute(attn_tc,
                         cudaFuncAttributeMaxDynamicSharedMemorySize, ATTN_SMEM);

    // 1) qkv = x @ Wqkv, scattered into g_q/g_k/g_v [B,H,T,D]
    gemm_tc<1><<<dim3(3072 / 256, NM / 128), 256, GEMM_SMEM>>>(
        x, Wqkv, nullptr, NM, 3 * NC, NC);

    // 2) causal attention -> g_att [B,T,C]
    attn_tc<<<dim3(NT / 64, NBH), 128, ATTN_SMEM>>>();

    // 3) out = g_att @ Wproj
    gemm_tc<2><<<dim3(NC / 256, NM / 128), 256, GEMM_SMEM>>>(
        nullptr, Wproj, out, NM, NC, NC);
}

// round 3
// speedup vs baseline: 2.8066x; 1.1573x over previous
#include <cuda_runtime.h>

// ---------------------------------------------------------------------------
// B=4, T=2048, C=1024, H=16, D=64.  All matmuls: mma.sync.m16n8k8.tf32.
// Inputs pre-rounded to tf32 (RN) once -> cp.async everywhere, no cvt in loops.
// ---------------------------------------------------------------------------

#define NBH 64
#define NT  2048
#define ND  64
#define NC  1024
#define NM  8192

__device__ float g_q[NBH * NT * ND];
__device__ float g_k[NBH * NT * ND];
__device__ float g_v[NBH * NT * ND];
__device__ float g_att[NM * NC];
__device__ float g_x[NM * NC];
__device__ float g_wqkv[NC * 3 * NC];
__device__ float g_wproj[NC * NC];

__device__ __forceinline__ unsigned f2tf(float f) {
    unsigned u;
    asm("cvt.rna.tf32.f32 %0, %1;" : "=r"(u) : "f"(f));
    return u;
}
__device__ __forceinline__ float rtf(float x) { return __uint_as_float(f2tf(x)); }

__device__ __forceinline__ void mma_tf32(float* c, const unsigned* a,
                                         unsigned b0, unsigned b1) {
    asm volatile(
        "mma.sync.aligned.m16n8k8.row.col.f32.tf32.tf32.f32 "
        "{%0,%1,%2,%3}, {%4,%5,%6,%7}, {%8,%9}, {%0,%1,%2,%3};"
        : "+f"(c[0]), "+f"(c[1]), "+f"(c[2]), "+f"(c[3])
        : "r"(a[0]), "r"(a[1]), "r"(a[2]), "r"(a[3]), "r"(b0), "r"(b1));
}

__device__ __forceinline__ void cp16(void* smem_dst, const void* gmem_src) {
    unsigned sa = (unsigned)__cvta_generic_to_shared(smem_dst);
    asm volatile("cp.async.cg.shared.global [%0], [%1], 16;" :: "r"(sa), "l"(gmem_src));
}
#define CPCOMMIT() asm volatile("cp.async.commit_group;")

// ---------------------------------------------------------------------------
// tf32 pre-round kernel (elementwise, float4)
// ---------------------------------------------------------------------------
__global__ void cvt_kernel(const float4* __restrict__ src,
                           uint4* __restrict__ dst, int n4)
{
    int i = blockIdx.x * 256 + threadIdx.x;
    if (i < n4) {
        float4 v = src[i];
        uint4 u;
        u.x = f2tf(v.x); u.y = f2tf(v.y); u.z = f2tf(v.z); u.w = f2tf(v.w);
        dst[i] = u;
    }
}

// ---------------------------------------------------------------------------
// GEMM: 128m x 256n x 16k tile, 256 threads (8 warps 2x4, 64x64 warp tile),
// 4-stage cp.async pipeline. A smem [m][k] stride 20, B smem [k][n] stride 264
// (both conflict-free for fragment LDS and 16B-aligned for cp.async).
// SCATTER=1: round + scatter into g_q/g_k/g_v.  SCATTER=0: plain store.
// ---------------------------------------------------------------------------
#define BM 128
#define BN 256
#define BK 16
#define STG 4
#define AST 20
#define BST 264
#define ASZ (BM * AST)      // 2560 floats / stage
#define BSZ (BK * BST)      // 4224 floats / stage
#define GEMM_SMEM (STG * (ASZ + BSZ) * 4)   // 108544 B

template <int SCATTER>
__global__ void __launch_bounds__(256, 1) gemm_tc(
    const float* __restrict__ A, const float* __restrict__ B,
    float* __restrict__ C, int M, int N, int K)
{
    extern __shared__ float sh[];
    float* As = sh;
    float* Bs = sh + STG * ASZ;

    const int tid  = threadIdx.x;
    const int lane = tid & 31;
    const int w    = tid >> 5;
    const int wm   = w >> 2;
    const int wn   = w & 3;
    const int g    = lane >> 2;
    const int cq   = lane & 3;
    const int bm   = blockIdx.y << 7;
    const int bn   = blockIdx.x << 8;

    const int NIT = K >> 4;

    // tile loader: stage s <- k-tile kt
    auto load_tile = [&](int kt, int s) {
        const float* Ag = A + (size_t)bm * K + kt * BK;
#pragma unroll
        for (int i = 0; i < 2; i++) {
            int c  = tid + i * 256;
            int r  = c >> 2;
            int kc = (c & 3) << 2;
            cp16(&As[s * ASZ + r * AST + kc], Ag + (size_t)r * K + kc);
        }
        const float* Bg = B + (size_t)kt * BK * N + bn;
#pragma unroll
        for (int i = 0; i < 4; i++) {
            int c  = tid + i * 256;
            int r  = c >> 6;
            int nc = (c & 63) << 2;
            cp16(&Bs[s * BSZ + r * BST + nc], Bg + (size_t)r * N + nc);
        }
    };

    float acc[4][8][4];
#pragma unroll
    for (int mi = 0; mi < 4; mi++)
#pragma unroll
        for (int ni = 0; ni < 8; ni++)
#pragma unroll
            for (int r = 0; r < 4; r++) acc[mi][ni][r] = 0.0f;

    // prologue: stages 0..2
#pragma unroll
    for (int s = 0; s < STG - 1; s++) { load_tile(s, s); CPCOMMIT(); }

#pragma unroll 1
    for (int kt = 0; kt < NIT; kt++) {
        asm volatile("cp.async.wait_group 2;");
        __syncthreads();

        if (kt + STG - 1 < NIT) load_tile(kt + STG - 1, (kt + STG - 1) & 3);
        CPCOMMIT();

        const float* Asb = As + (kt & 3) * ASZ;
        const float* Bsb = Bs + (kt & 3) * BSZ;

#pragma unroll
        for (int ks = 0; ks < 2; ks++) {
            unsigned af[4][4], bf[8][2];
#pragma unroll
            for (int mi = 0; mi < 4; mi++) {
                const int row = wm * 64 + mi * 16 + g;
                const float* pa = Asb + row * AST + ks * 8 + cq;
                af[mi][0] = __float_as_uint(pa[0]);
                af[mi][1] = __float_as_uint(pa[8 * AST]);
                af[mi][2] = __float_as_uint(pa[4]);
                af[mi][3] = __float_as_uint(pa[8 * AST + 4]);
            }
#pragma unroll
            for (int ni = 0; ni < 8; ni++) {
                const int col = wn * 64 + ni * 8 + g;
                const float* pb = Bsb + (ks * 8 + cq) * BST + col;
                bf[ni][0] = __float_as_uint(pb[0]);
                bf[ni][1] = __float_as_uint(pb[4 * BST]);
            }
#pragma unroll
            for (int mi = 0; mi < 4; mi++)
#pragma unroll
                for (int ni = 0; ni < 8; ni++)
                    mma_tf32(acc[mi][ni], af[mi], bf[ni][0], bf[ni][1]);
        }
    }

    // epilogue
#pragma unroll
    for (int mi = 0; mi < 4; mi++) {
        const int row = bm + wm * 64 + mi * 16 + g;
#pragma unroll
        for (int ni = 0; ni < 8; ni++) {
            const int col = bn + wn * 64 + ni * 8 + 2 * cq;
            if (SCATTER) {
                const int which = col >> 10;
                const int h     = (col & 1023) >> 6;
                const int d0    = col & 63;
                float* dst = (which == 0) ? g_q : (which == 1) ? g_k : g_v;
                {
                    const int b = row >> 11, t = row & 2047;
                    float* p = dst + ((size_t)((b * 16 + h) * 2048 + t) << 6) + d0;
                    *(float2*)p = make_float2(rtf(acc[mi][ni][0]), rtf(acc[mi][ni][1]));
                }
                {
                    const int r2 = row + 8;
                    const int b = r2 >> 11, t = r2 & 2047;
                    float* p = dst + ((size_t)((b * 16 + h) * 2048 + t) << 6) + d0;
                    *(float2*)p = make_float2(rtf(acc[mi][ni][2]), rtf(acc[mi][ni][3]));
                }
            } else {
                *(float2*)&C[(size_t)row * N + col] =
                    make_float2(acc[mi][ni][0], acc[mi][ni][1]);
                *(float2*)&C[(size_t)(row + 8) * N + col] =
                    make_float2(acc[mi][ni][2], acc[mi][ni][3]);
            }
        }
    }
}

// ---------------------------------------------------------------------------
// Causal flash attention, tf32 tensor cores, 256 threads = 8 warps.
// Block handles 128 q rows; warp w owns rows [w*16, w*16+16).
// K/V tiles (64x64) double-buffered via cp.async. Q/K/V pre-rounded tf32.
// ---------------------------------------------------------------------------
#define ATS 72
#define AQ  (128 * ATS)
#define AKV (64 * ATS)
#define ATTN_SMEM ((AQ + 4 * AKV + 128 * ATS) * 4)   // 147456 B

__global__ void __launch_bounds__(256, 1) attn_tc()
{
    extern __shared__ float sh[];
    float* Qs = sh;                    // [128][ATS]
    float* Ks = sh + AQ;               // [2][64][ATS]
    float* Vs = sh + AQ + 2 * AKV;     // [2][64][ATS]
    float* Ps = sh + AQ + 4 * AKV;     // [128][ATS]

    const int tid  = threadIdx.x;
    const int lane = tid & 31;
    const int w    = tid >> 5;
    const int g    = lane >> 2;
    const int cq   = lane & 3;
    const int bh   = blockIdx.y;
    const int q0   = blockIdx.x << 7;

    const float* Qg  = g_q + ((size_t)bh * NT + q0) * ND;
    const float* Kg0 = g_k + (size_t)bh * NT * ND;
    const float* Vg0 = g_v + (size_t)bh * NT * ND;

    auto load_kv = [&](int kt, int s) {
        const float* Kg = Kg0 + ((size_t)kt << 12);
        const float* Vg = Vg0 + ((size_t)kt << 12);
#pragma unroll
        for (int i = 0; i < 4; i++) {
            int c  = tid + i * 256;
            int r  = c >> 4;
            int c4 = (c & 15) << 2;
            cp16(&Ks[s * AKV + r * ATS + c4], Kg + r * 64 + c4);
            cp16(&Vs[s * AKV + r * ATS + c4], Vg + r * 64 + c4);
        }
    };

    // group 0: Q + K0/V0
#pragma unroll
    for (int i = 0; i < 8; i++) {
        int c  = tid + i * 256;
        int r  = c >> 4;
        int c4 = (c & 15) << 2;
        cp16(&Qs[r * ATS + c4], Qg + r * 64 + c4);
    }
    load_kv(0, 0);
    CPCOMMIT();

    float m0 = -1e30f, m1 = -1e30f, l0 = 0.0f, l1 = 0.0f;
    float o[8][4];
#pragma unroll
    for (int nt = 0; nt < 8; nt++)
#pragma unroll
        for (int r = 0; r < 4; r++) o[nt][r] = 0.0f;

    const int rq    = w * 16 + g;
    const int ktmax = (q0 >> 6) + 1;

    for (int kt = 0; kt <= ktmax; kt++) {
        asm volatile("cp.async.wait_group 0;");
        __syncthreads();

        if (kt < ktmax) load_kv(kt + 1, (kt + 1) & 1);
        CPCOMMIT();

        // skip warp-tiles that are fully masked (tile cols all > warp's rows)
        if (kt * 64 <= q0 + w * 16 + 15) {
            const float* Kb = Ks + (kt & 1) * AKV;
            const float* Vb = Vs + (kt & 1) * AKV;

            float s[8][4];
#pragma unroll
            for (int nt = 0; nt < 8; nt++)
#pragma unroll
                for (int r = 0; r < 4; r++) s[nt][r] = 0.0f;

#pragma unroll
            for (int ks = 0; ks < 8; ks++) {
                unsigned af[4];
                const float* pq = Qs + rq * ATS + ks * 8 + cq;
                af[0] = __float_as_uint(pq[0]);
                af[1] = __float_as_uint(pq[8 * ATS]);
                af[2] = __float_as_uint(pq[4]);
                af[3] = __float_as_uint(pq[8 * ATS + 4]);
#pragma unroll
                for (int nt = 0; nt < 8; nt++) {
                    const float* pk = Kb + (nt * 8 + g) * ATS + ks * 8 + cq;
                    mma_tf32(s[nt], af, __float_as_uint(pk[0]),
                             __float_as_uint(pk[4]));
                }
            }

#pragma unroll
            for (int nt = 0; nt < 8; nt++)
#pragma unroll
                for (int r = 0; r < 4; r++) s[nt][r] *= 0.125f;

            if (kt * 64 + 63 > q0 + w * 16) {   // diagonal tile: mask
                const int r0 = q0 + rq, r1 = q0 + rq + 8;
#pragma unroll
                for (int nt = 0; nt < 8; nt++) {
                    int gc = kt * 64 + nt * 8 + 2 * cq;
                    if (gc     > r0) s[nt][0] = -1e30f;
                    if (gc + 1 > r0) s[nt][1] = -1e30f;
                    if (gc     > r1) s[nt][2] = -1e30f;
                    if (gc + 1 > r1) s[nt][3] = -1e30f;
                }
            }

            // online softmax
            float rm0 = -1e30f, rm1 = -1e30f;
#pragma unroll
            for (int nt = 0; nt < 8; nt++) {
                rm0 = fmaxf(rm0, fmaxf(s[nt][0], s[nt][1]));
                rm1 = fmaxf(rm1, fmaxf(s[nt][2], s[nt][3]));
            }
            rm0 = fmaxf(rm0, __shfl_xor_sync(0xffffffffu, rm0, 1));
            rm0 = fmaxf(rm0, __shfl_xor_sync(0xffffffffu, rm0, 2));
            rm1 = fmaxf(rm1, __shfl_xor_sync(0xffffffffu, rm1, 1));
            rm1 = fmaxf(rm1, __shfl_xor_sync(0xffffffffu, rm1, 2));

            float mn0 = fmaxf(m0, rm0), mn1 = fmaxf(m1, rm1);
            float sc0 = __expf(m0 - mn0), sc1 = __expf(m1 - mn1);
            float rs0 = 0.0f, rs1 = 0.0f;
#pragma unroll
            for (int nt = 0; nt < 8; nt++) {
                s[nt][0] = __expf(s[nt][0] - mn0);
                s[nt][1] = __expf(s[nt][1] - mn0);
                s[nt][2] = __expf(s[nt][2] - mn1);
                s[nt][3] = __expf(s[nt][3] - mn1);
                rs0 += s[nt][0] + s[nt][1];
                rs1 += s[nt][2] + s[nt][3];
            }
            rs0 += __shfl_xor_sync(0xffffffffu, rs0, 1);
            rs0 += __shfl_xor_sync(0xffffffffu, rs0, 2);
            rs1 += __shfl_xor_sync(0xffffffffu, rs1, 1);
            rs1 += __shfl_xor_sync(0xffffffffu, rs1, 2);
            l0 = l0 * sc0 + rs0;
            l1 = l1 * sc1 + rs1;
            m0 = mn0; m1 = mn1;
#pragma unroll
            for (int nt = 0; nt < 8; nt++) {
                o[nt][0] *= sc0; o[nt][1] *= sc0;
                o[nt][2] *= sc1; o[nt][3] *= sc1;
            }

            // P -> smem (warp-private rows), rounded
#pragma unroll
            for (int nt = 0; nt < 8; nt++) {
                *(float2*)&Ps[rq * ATS + nt * 8 + 2 * cq] =
                    make_float2(rtf(s[nt][0]), rtf(s[nt][1]));
                *(float2*)&Ps[(rq + 8) * ATS + nt * 8 + 2 * cq] =
                    make_float2(rtf(s[nt][2]), rtf(s[nt][3]));
            }
            __syncwarp();

            // O += P V
#pragma unroll
            for (int ks = 0; ks < 8; ks++) {
                unsigned af[4];
                const float* pp = Ps + rq * ATS + ks * 8 + cq;
                af[0] = __float_as_uint(pp[0]);
                af[1] = __float_as_uint(pp[8 * ATS]);
                af[2] = __float_as_uint(pp[4]);
                af[3] = __float_as_uint(pp[8 * ATS + 4]);
#pragma unroll
                for (int nt = 0; nt < 8; nt++) {
                    const float* pv = Vb + (ks * 8 + cq) * ATS + nt * 8 + g;
                    mma_tf32(o[nt], af, __float_as_uint(pv[0]),
                             __float_as_uint(pv[4 * ATS]));
                }
            }
            __syncwarp();
        }
    }

    // epilogue: attOut[b][t][h*64+d], rounded for gemm2's async path
    const int b = bh >> 4;
    const int h = bh & 15;
    const float inv0 = 1.0f / l0;
    const float inv1 = 1.0f / l1;
    float* Og = g_att + ((size_t)(b * NT + q0 + rq)) * NC + (h << 6);
#pragma unroll
    for (int nt = 0; nt < 8; nt++) {
        int col = nt * 8 + 2 * cq;
        *(float2*)(Og + col) =
            make_float2(rtf(o[nt][0] * inv0), rtf(o[nt][1] * inv0));
        *(float2*)(Og + (size_t)8 * NC + col) =
            make_float2(rtf(o[nt][2] * inv1), rtf(o[nt][3] * inv1));
    }
}

// ---------------------------------------------------------------------------
// launch
// ---------------------------------------------------------------------------
extern "C" void kernel_launch(void* const* d_in, const int* in_sizes, int n_in,
                              void* d_out, int out_size)
{
    const float* x     = (const float*)d_in[0];
    const float* Wqkv  = (const float*)d_in[1];
    const float* Wproj = (const float*)d_in[2];
    float* out = (float*)d_out;

    void *px, *pwqkv, *pwproj, *patt;
    cudaGetSymbolAddress(&px, g_x);
    cudaGetSymbolAddress(&pwqkv, g_wqkv);
    cudaGetSymbolAddress(&pwproj, g_wproj);
    cudaGetSymbolAddress(&patt, g_att);

    cudaFuncSetAttribute(gemm_tc<1>,
                         cudaFuncAttributeMaxDynamicSharedMemorySize, GEMM_SMEM);
    cudaFuncSetAttribute(gemm_tc<0>,
                         cudaFuncAttributeMaxDynamicSharedMemorySize, GEMM_SMEM);
    cudaFuncSetAttribute(attn_tc,
                         cudaFuncAttributeMaxDynamicSharedMemorySize, ATTN_SMEM);

    // 0) pre-round inputs to tf32
    cvt_kernel<<<(NM * NC / 4 + 255) / 256, 256>>>(
        (const float4*)x, (uint4*)px, NM * NC / 4);
    cvt_kernel<<<(NC * 3 * NC / 4 + 255) / 256, 256>>>(
        (const float4*)Wqkv, (uint4*)pwqkv, NC * 3 * NC / 4);
    cvt_kernel<<<(NC * NC / 4 + 255) / 256, 256>>>(
        (const float4*)Wproj, (uint4*)pwproj, NC * NC / 4);

    // 1) qkv = x @ Wqkv -> scatter (rounded) into g_q/g_k/g_v
    gemm_tc<1><<<dim3(3 * NC / BN, NM / BM), 256, GEMM_SMEM>>>(
        (const float*)px, (const float*)pwqkv, nullptr, NM, 3 * NC, NC);

    // 2) causal attention -> g_att (rounded)
    attn_tc<<<dim3(NT / 128, NBH), 256, ATTN_SMEM>>>();

    // 3) out = g_att @ Wproj
    gemm_tc<0><<<dim3(NC / BN, NM / BM), 256, GEMM_SMEM>>>(
        (const float*)patt, (const float*)pwproj, out, NM, NC, NC);
}

// round 4
// speedup vs baseline: 2.9057x; 1.0353x over previous
#include <cuda_runtime.h>

// ---------------------------------------------------------------------------
// B=4, T=2048, C=1024, H=16, D=64.  All matmuls: mma.sync.m16n8k8.tf32.
// Inputs pre-rounded to tf32 (RN) once -> cp.async everywhere, no cvt in loops.
// GEMM: 128x128 tile, 2 CTAs/SM for latency hiding.
// ---------------------------------------------------------------------------

#define NBH 64
#define NT  2048
#define ND  64
#define NC  1024
#define NM  8192

__device__ float g_q[NBH * NT * ND];
__device__ float g_k[NBH * NT * ND];
__device__ float g_v[NBH * NT * ND];
__device__ float g_att[NM * NC];
__device__ float g_x[NM * NC];
__device__ float g_wqkv[NC * 3 * NC];
__device__ float g_wproj[NC * NC];

__device__ __forceinline__ unsigned f2tf(float f) {
    unsigned u;
    asm("cvt.rna.tf32.f32 %0, %1;" : "=r"(u) : "f"(f));
    return u;
}
__device__ __forceinline__ float rtf(float x) { return __uint_as_float(f2tf(x)); }

__device__ __forceinline__ void mma_tf32(float* c, const unsigned* a,
                                         unsigned b0, unsigned b1) {
    asm volatile(
        "mma.sync.aligned.m16n8k8.row.col.f32.tf32.tf32.f32 "
        "{%0,%1,%2,%3}, {%4,%5,%6,%7}, {%8,%9}, {%0,%1,%2,%3};"
        : "+f"(c[0]), "+f"(c[1]), "+f"(c[2]), "+f"(c[3])
        : "r"(a[0]), "r"(a[1]), "r"(a[2]), "r"(a[3]), "r"(b0), "r"(b1));
}

__device__ __forceinline__ void cp16(void* smem_dst, const void* gmem_src) {
    unsigned sa = (unsigned)__cvta_generic_to_shared(smem_dst);
    asm volatile("cp.async.cg.shared.global [%0], [%1], 16;" :: "r"(sa), "l"(gmem_src));
}
#define CPCOMMIT() asm volatile("cp.async.commit_group;")

__device__ __forceinline__ float fexp2(float x) {
    float y;
    asm("ex2.approx.f32 %0, %1;" : "=f"(y) : "f"(x));
    return y;
}

// ---------------------------------------------------------------------------
// tf32 pre-round kernel
// ---------------------------------------------------------------------------
__global__ void cvt_kernel(const float4* __restrict__ src,
                           uint4* __restrict__ dst, int n4)
{
    int i = blockIdx.x * 256 + threadIdx.x;
    if (i < n4) {
        float4 v = src[i];
        uint4 u;
        u.x = f2tf(v.x); u.y = f2tf(v.y); u.z = f2tf(v.z); u.w = f2tf(v.w);
        dst[i] = u;
    }
}

// ---------------------------------------------------------------------------
// GEMM: 128m x 128n x 16k tile, 256 threads (8 warps 2x4, warp tile 64x32),
// 4-stage cp.async pipeline, 2 CTAs/SM.
// A smem [m][k] stride 20, B smem [k][n] stride 136 (both ≡8 mod 32).
// SCATTER=1: round + scatter into g_q/g_k/g_v.  SCATTER=0: plain store.
// ---------------------------------------------------------------------------
#define BM 128
#define BN 128
#define BK 16
#define STG 4
#define AST 20
#define BST 136
#define ASZ (BM * AST)      // 2560 floats / stage
#define BSZ (BK * BST)      // 2176 floats / stage
#define GEMM_SMEM (STG * (ASZ + BSZ) * 4)   // 75776 B

template <int SCATTER>
__global__ void __launch_bounds__(256, 2) gemm_tc(
    const float* __restrict__ A, const float* __restrict__ B,
    float* __restrict__ C, int M, int N, int K)
{
    extern __shared__ float sh[];
    float* As = sh;
    float* Bs = sh + STG * ASZ;

    const int tid  = threadIdx.x;
    const int lane = tid & 31;
    const int w    = tid >> 5;
    const int wm   = w >> 2;          // 0..1 -> m*64
    const int wn   = w & 3;           // 0..3 -> n*32
    const int g    = lane >> 2;
    const int cq   = lane & 3;
    const int bm   = blockIdx.y << 7;
    const int bn   = blockIdx.x << 7;

    const int NIT = K >> 4;

    auto load_tile = [&](int kt, int s) {
        const float* Ag = A + (size_t)bm * K + kt * BK;
#pragma unroll
        for (int i = 0; i < 2; i++) {
            int c  = tid + i * 256;
            int r  = c >> 2;
            int kc = (c & 3) << 2;
            cp16(&As[s * ASZ + r * AST + kc], Ag + (size_t)r * K + kc);
        }
        const float* Bg = B + (size_t)kt * BK * N + bn;
#pragma unroll
        for (int i = 0; i < 2; i++) {
            int c  = tid + i * 256;
            int r  = c >> 5;
            int nc = (c & 31) << 2;
            cp16(&Bs[s * BSZ + r * BST + nc], Bg + (size_t)r * N + nc);
        }
    };

    float acc[4][4][4];
#pragma unroll
    for (int mi = 0; mi < 4; mi++)
#pragma unroll
        for (int ni = 0; ni < 4; ni++)
#pragma unroll
            for (int r = 0; r < 4; r++) acc[mi][ni][r] = 0.0f;

#pragma unroll
    for (int s = 0; s < STG - 1; s++) { load_tile(s, s); CPCOMMIT(); }

#pragma unroll 1
    for (int kt = 0; kt < NIT; kt++) {
        asm volatile("cp.async.wait_group 2;");
        __syncthreads();

        if (kt + STG - 1 < NIT) load_tile(kt + STG - 1, (kt + STG - 1) & 3);
        CPCOMMIT();

        const float* Asb = As + (kt & 3) * ASZ;
        const float* Bsb = Bs + (kt & 3) * BSZ;

#pragma unroll
        for (int ks = 0; ks < 2; ks++) {
            unsigned af[4][4], bf[4][2];
#pragma unroll
            for (int mi = 0; mi < 4; mi++) {
                const int row = wm * 64 + mi * 16 + g;
                const float* pa = Asb + row * AST + ks * 8 + cq;
                af[mi][0] = __float_as_uint(pa[0]);
                af[mi][1] = __float_as_uint(pa[8 * AST]);
                af[mi][2] = __float_as_uint(pa[4]);
                af[mi][3] = __float_as_uint(pa[8 * AST + 4]);
            }
#pragma unroll
            for (int ni = 0; ni < 4; ni++) {
                const int col = wn * 32 + ni * 8 + g;
                const float* pb = Bsb + (ks * 8 + cq) * BST + col;
                bf[ni][0] = __float_as_uint(pb[0]);
                bf[ni][1] = __float_as_uint(pb[4 * BST]);
            }
#pragma unroll
            for (int mi = 0; mi < 4; mi++)
#pragma unroll
                for (int ni = 0; ni < 4; ni++)
                    mma_tf32(acc[mi][ni], af[mi], bf[ni][0], bf[ni][1]);
        }
    }

    // epilogue
#pragma unroll
    for (int mi = 0; mi < 4; mi++) {
        const int row = bm + wm * 64 + mi * 16 + g;
#pragma unroll
        for (int ni = 0; ni < 4; ni++) {
            const int col = bn + wn * 32 + ni * 8 + 2 * cq;
            if (SCATTER) {
                const int which = col >> 10;
                const int h     = (col & 1023) >> 6;
                const int d0    = col & 63;
                float* dst = (which == 0) ? g_q : (which == 1) ? g_k : g_v;
                {
                    const int b = row >> 11, t = row & 2047;
                    float* p = dst + ((size_t)((b * 16 + h) * 2048 + t) << 6) + d0;
                    *(float2*)p = make_float2(rtf(acc[mi][ni][0]), rtf(acc[mi][ni][1]));
                }
                {
                    const int r2 = row + 8;
                    const int b = r2 >> 11, t = r2 & 2047;
                    float* p = dst + ((size_t)((b * 16 + h) * 2048 + t) << 6) + d0;
                    *(float2*)p = make_float2(rtf(acc[mi][ni][2]), rtf(acc[mi][ni][3]));
                }
            } else {
                *(float2*)&C[(size_t)row * N + col] =
                    make_float2(acc[mi][ni][0], acc[mi][ni][1]);
                *(float2*)&C[(size_t)(row + 8) * N + col] =
                    make_float2(acc[mi][ni][2], acc[mi][ni][3]);
            }
        }
    }
}

// ---------------------------------------------------------------------------
// Causal flash attention, tf32 tensor cores, 256 threads = 8 warps.
// Block handles 128 q rows; warp w owns rows [w*16, w*16+16).
// K/V tiles (64x64) double-buffered via cp.async. Softmax in log2 domain.
// ---------------------------------------------------------------------------
#define ATS 72
#define AQ  (128 * ATS)
#define AKV (64 * ATS)
#define ATTN_SMEM ((AQ + 4 * AKV + 128 * ATS) * 4)   // 147456 B
#define SCL 0.180336880f   // 0.125 * log2(e)

__global__ void __launch_bounds__(256, 1) attn_tc()
{
    extern __shared__ float sh[];
    float* Qs = sh;                    // [128][ATS]
    float* Ks = sh + AQ;               // [2][64][ATS]
    float* Vs = sh + AQ + 2 * AKV;     // [2][64][ATS]
    float* Ps = sh + AQ + 4 * AKV;     // [128][ATS]

    const int tid  = threadIdx.x;
    const int lane = tid & 31;
    const int w    = tid >> 5;
    const int g    = lane >> 2;
    const int cq   = lane & 3;
    const int bh   = blockIdx.y;
    const int q0   = blockIdx.x << 7;

    const float* Qg  = g_q + ((size_t)bh * NT + q0) * ND;
    const float* Kg0 = g_k + (size_t)bh * NT * ND;
    const float* Vg0 = g_v + (size_t)bh * NT * ND;

    auto load_kv = [&](int kt, int s) {
        const float* Kg = Kg0 + ((size_t)kt << 12);
        const float* Vg = Vg0 + ((size_t)kt << 12);
#pragma unroll
        for (int i = 0; i < 4; i++) {
            int c  = tid + i * 256;
            int r  = c >> 4;
            int c4 = (c & 15) << 2;
            cp16(&Ks[s * AKV + r * ATS + c4], Kg + r * 64 + c4);
            cp16(&Vs[s * AKV + r * ATS + c4], Vg + r * 64 + c4);
        }
    };

#pragma unroll
    for (int i = 0; i < 8; i++) {
        int c  = tid + i * 256;
        int r  = c >> 4;
        int c4 = (c & 15) << 2;
        cp16(&Qs[r * ATS + c4], Qg + r * 64 + c4);
    }
    load_kv(0, 0);
    CPCOMMIT();

    float m0 = -1e30f, m1 = -1e30f, l0 = 0.0f, l1 = 0.0f;
    float o[8][4];
#pragma unroll
    for (int nt = 0; nt < 8; nt++)
#pragma unroll
        for (int r = 0; r < 4; r++) o[nt][r] = 0.0f;

    const int rq    = w * 16 + g;
    const int ktmax = (q0 >> 6) + 1;

    for (int kt = 0; kt <= ktmax; kt++) {
        asm volatile("cp.async.wait_group 0;");
        __syncthreads();

        if (kt < ktmax) load_kv(kt + 1, (kt + 1) & 1);
        CPCOMMIT();

        if (kt * 64 <= q0 + w * 16 + 15) {
            const float* Kb = Ks + (kt & 1) * AKV;
            const float* Vb = Vs + (kt & 1) * AKV;

            float s[8][4];
#pragma unroll
            for (int nt = 0; nt < 8; nt++)
#pragma unroll
                for (int r = 0; r < 4; r++) s[nt][r] = 0.0f;

#pragma unroll
            for (int ks = 0; ks < 8; ks++) {
                unsigned af[4];
                const float* pq = Qs + rq * ATS + ks * 8 + cq;
                af[0] = __float_as_uint(pq[0]);
                af[1] = __float_as_uint(pq[8 * ATS]);
                af[2] = __float_as_uint(pq[4]);
                af[3] = __float_as_uint(pq[8 * ATS + 4]);
#pragma unroll
                for (int nt = 0; nt < 8; nt++) {
                    const float* pk = Kb + (nt * 8 + g) * ATS + ks * 8 + cq;
                    mma_tf32(s[nt], af, __float_as_uint(pk[0]),
                             __float_as_uint(pk[4]));
                }
            }

            // scale into log2 domain
#pragma unroll
            for (int nt = 0; nt < 8; nt++)
#pragma unroll
                for (int r = 0; r < 4; r++) s[nt][r] *= SCL;

            if (kt * 64 + 63 > q0 + w * 16) {   // diagonal tile: mask
                const int r0 = q0 + rq, r1 = q0 + rq + 8;
#pragma unroll
                for (int nt = 0; nt < 8; nt++) {
                    int gc = kt * 64 + nt * 8 + 2 * cq;
                    if (gc     > r0) s[nt][0] = -1e30f;
                    if (gc + 1 > r0) s[nt][1] = -1e30f;
                    if (gc     > r1) s[nt][2] = -1e30f;
                    if (gc + 1 > r1) s[nt][3] = -1e30f;
                }
            }

            // online softmax (log2 domain)
            float rm0 = -1e30f, rm1 = -1e30f;
#pragma unroll
            for (int nt = 0; nt < 8; nt++) {
                rm0 = fmaxf(rm0, fmaxf(s[nt][0], s[nt][1]));
                rm1 = fmaxf(rm1, fmaxf(s[nt][2], s[nt][3]));
            }
            rm0 = fmaxf(rm0, __shfl_xor_sync(0xffffffffu, rm0, 1));
            rm0 = fmaxf(rm0, __shfl_xor_sync(0xffffffffu, rm0, 2));
            rm1 = fmaxf(rm1, __shfl_xor_sync(0xffffffffu, rm1, 1));
            rm1 = fmaxf(rm1, __shfl_xor_sync(0xffffffffu, rm1, 2));

            float mn0 = fmaxf(m0, rm0), mn1 = fmaxf(m1, rm1);
            float sc0 = fexp2(m0 - mn0), sc1 = fexp2(m1 - mn1);
            float rs0 = 0.0f, rs1 = 0.0f;
#pragma unroll
            for (int nt = 0; nt < 8; nt++) {
                s[nt][0] = fexp2(s[nt][0] - mn0);
                s[nt][1] = fexp2(s[nt][1] - mn0);
                s[nt][2] = fexp2(s[nt][2] - mn1);
                s[nt][3] = fexp2(s[nt][3] - mn1);
                rs0 += s[nt][0] + s[nt][1];
                rs1 += s[nt][2] + s[nt][3];
            }
            rs0 += __shfl_xor_sync(0xffffffffu, rs0, 1);
            rs0 += __shfl_xor_sync(0xffffffffu, rs0, 2);
            rs1 += __shfl_xor_sync(0xffffffffu, rs1, 1);
            rs1 += __shfl_xor_sync(0xffffffffu, rs1, 2);
            l0 = l0 * sc0 + rs0;
            l1 = l1 * sc1 + rs1;
            m0 = mn0; m1 = mn1;
#pragma unroll
            for (int nt = 0; nt < 8; nt++) {
                o[nt][0] *= sc0; o[nt][1] *= sc0;
                o[nt][2] *= sc1; o[nt][3] *= sc1;
            }

#pragma unroll
            for (int nt = 0; nt < 8; nt++) {
                *(float2*)&Ps[rq * ATS + nt * 8 + 2 * cq] =
                    make_float2(rtf(s[nt][0]), rtf(s[nt][1]));
                *(float2*)&Ps[(rq + 8) * ATS + nt * 8 + 2 * cq] =
                    make_float2(rtf(s[nt][2]), rtf(s[nt][3]));
            }
            __syncwarp();

#pragma unroll
            for (int ks = 0; ks < 8; ks++) {
                unsigned af[4];
                const float* pp = Ps + rq * ATS + ks * 8 + cq;
                af[0] = __float_as_uint(pp[0]);
                af[1] = __float_as_uint(pp[8 * ATS]);
                af[2] = __float_as_uint(pp[4]);
                af[3] = __float_as_uint(pp[8 * ATS + 4]);
#pragma unroll
                for (int nt = 0; nt < 8; nt++) {
                    const float* pv = Vb + (ks * 8 + cq) * ATS + nt * 8 + g;
                    mma_tf32(o[nt], af, __float_as_uint(pv[0]),
                             __float_as_uint(pv[4 * ATS]));
                }
            }
            __syncwarp();
        }
    }

    const int b = bh >> 4;
    const int h = bh & 15;
    const float inv0 = 1.0f / l0;
    const float inv1 = 1.0f / l1;
    float* Og = g_att + ((size_t)(b * NT + q0 + rq)) * NC + (h << 6);
#pragma unroll
    for (int nt = 0; nt < 8; nt++) {
        int col = nt * 8 + 2 * cq;
        *(float2*)(Og + col) =
            make_float2(rtf(o[nt][0] * inv0), rtf(o[nt][1] * inv0));
        *(float2*)(Og + (size_t)8 * NC + col) =
            make_float2(rtf(o[nt][2] * inv1), rtf(o[nt][3] * inv1));
    }
}

// ---------------------------------------------------------------------------
// launch
// ---------------------------------------------------------------------------
extern "C" void kernel_launch(void* const* d_in, const int* in_sizes, int n_in,
                              void* d_out, int out_size)
{
    const float* x     = (const float*)d_in[0];
    const float* Wqkv  = (const float*)d_in[1];
    const float* Wproj = (const float*)d_in[2];
    float* out = (float*)d_out;

    void *px, *pwqkv, *pwproj, *patt;
    cudaGetSymbolAddress(&px, g_x);
    cudaGetSymbolAddress(&pwqkv, g_wqkv);
    cudaGetSymbolAddress(&pwproj, g_wproj);
    cudaGetSymbolAddress(&patt, g_att);

    cudaFuncSetAttribute(gemm_tc<1>,
                         cudaFuncAttributeMaxDynamicSharedMemorySize, GEMM_SMEM);
    cudaFuncSetAttribute(gemm_tc<0>,
                         cudaFuncAttributeMaxDynamicSharedMemorySize, GEMM_SMEM);
    cudaFuncSetAttribute(attn_tc,
                         cudaFuncAttributeMaxDynamicSharedMemorySize, ATTN_SMEM);

    // 0) pre-round inputs to tf32
    cvt_kernel<<<(NM * NC / 4 + 255) / 256, 256>>>(
        (const float4*)x, (uint4*)px, NM * NC / 4);
    cvt_kernel<<<(NC * 3 * NC / 4 + 255) / 256, 256>>>(
        (const float4*)Wqkv, (uint4*)pwqkv, NC * 3 * NC / 4);
    cvt_kernel<<<(NC * NC / 4 + 255) / 256, 256>>>(
        (const float4*)Wproj, (uint4*)pwproj, NC * NC / 4);

    // 1) qkv = x @ Wqkv -> scatter (rounded) into g_q/g_k/g_v
    gemm_tc<1><<<dim3(3 * NC / BN, NM / BM), 256, GEMM_SMEM>>>(
        (const float*)px, (const float*)pwqkv, nullptr, NM, 3 * NC, NC);

    // 2) causal attention -> g_att (rounded)
    attn_tc<<<dim3(NT / 128, NBH), 256, ATTN_SMEM>>>();

    // 3) out = g_att @ Wproj
    gemm_tc<0><<<dim3(NC / BN, NM / BM), 256, GEMM_SMEM>>>(
        (const float*)patt, (const float*)pwproj, out, NM, NC, NC);
}

// round 6
// speedup vs baseline: 3.5111x; 1.2084x over previous
#include <cuda_runtime.h>

// ---------------------------------------------------------------------------
// B=4, T=2048, C=1024, H=16, D=64.  All matmuls: mma.sync.m16n8k8.tf32.
// Fragment loads via ldmatrix.x4 (b16 trick for tf32). B operands n-major.
// V stored transposed [B,H,D,T] by the QKV epilogue for the PV matmul.
// ---------------------------------------------------------------------------

#define NBH 64
#define NT  2048
#define ND  64
#define NC  1024
#define NM  8192

__device__ float g_q[NBH * NT * ND];
__device__ float g_k[NBH * NT * ND];
__device__ float g_v[NBH * NT * ND];        // transposed: [bh][d][t]
__device__ float g_att[NM * NC];
__device__ float g_x[NM * NC];
__device__ float g_wqkv[3 * NC * NC];       // transposed: [n][k]
__device__ float g_wproj[NC * NC];          // transposed: [n][k]

__device__ __forceinline__ unsigned f2tf(float f) {
    unsigned u;
    asm("cvt.rna.tf32.f32 %0, %1;" : "=r"(u) : "f"(f));
    return u;
}
__device__ __forceinline__ float rtf(float x) { return __uint_as_float(f2tf(x)); }

__device__ __forceinline__ void mma_tf32(float* c, const unsigned* a,
                                         unsigned b0, unsigned b1) {
    asm volatile(
        "mma.sync.aligned.m16n8k8.row.col.f32.tf32.tf32.f32 "
        "{%0,%1,%2,%3}, {%4,%5,%6,%7}, {%8,%9}, {%0,%1,%2,%3};"
        : "+f"(c[0]), "+f"(c[1]), "+f"(c[2]), "+f"(c[3])
        : "r"(a[0]), "r"(a[1]), "r"(a[2]), "r"(a[3]), "r"(b0), "r"(b1));
}

__device__ __forceinline__ void ldsm4(unsigned* r, const float* p) {
    unsigned a = (unsigned)__cvta_generic_to_shared(p);
    asm volatile("ldmatrix.sync.aligned.m8n8.x4.shared.b16 {%0,%1,%2,%3}, [%4];"
                 : "=r"(r[0]), "=r"(r[1]), "=r"(r[2]), "=r"(r[3]) : "r"(a));
}

__device__ __forceinline__ void cp16(void* smem_dst, const void* gmem_src) {
    unsigned sa = (unsigned)__cvta_generic_to_shared(smem_dst);
    asm volatile("cp.async.cg.shared.global [%0], [%1], 16;" :: "r"(sa), "l"(gmem_src));
}
#define CPCOMMIT() asm volatile("cp.async.commit_group;")

__device__ __forceinline__ float fexp2(float x) {
    float y;
    asm("ex2.approx.f32 %0, %1;" : "=f"(y) : "f"(x));
    return y;
}

// swizzles (chunk = 4-float group index within a row)
#define SWG(r, c) ((c) ^ (((r) >> 1) & 3))   // rows of 16 floats (GEMM)
#define SWA(r, c) ((c) ^ ((r) & 7))          // rows of 64 floats (attention)

// ---------------------------------------------------------------------------
// pre-round kernels
// ---------------------------------------------------------------------------
__global__ void cvt_kernel(const float4* __restrict__ src,
                           uint4* __restrict__ dst, int n4)
{
    int i = blockIdx.x * 256 + threadIdx.x;
    if (i < n4) {
        float4 v = src[i];
        uint4 u;
        u.x = f2tf(v.x); u.y = f2tf(v.y); u.z = f2tf(v.z); u.w = f2tf(v.w);
        dst[i] = u;
    }
}

// round + transpose W[K][N] -> Wt[N][K]
__global__ void cvt_t_kernel(const float* __restrict__ src,
                             float* __restrict__ dst, int K, int N)
{
    __shared__ float t[32][33];
    const int n0 = blockIdx.x << 5;
    const int k0 = blockIdx.y << 5;
    const int tx = threadIdx.x & 31;
    const int ty = threadIdx.x >> 5;   // 0..7
#pragma unroll
    for (int j = 0; j < 4; j++)
        t[ty + j * 8][tx] = src[(size_t)(k0 + ty + j * 8) * N + n0 + tx];
    __syncthreads();
#pragma unroll
    for (int j = 0; j < 4; j++)
        dst[(size_t)(n0 + ty + j * 8) * K + k0 + tx] = rtf(t[tx][ty + j * 8]);
}

// ---------------------------------------------------------------------------
// GEMM: 128m x 128n x 16k tile, 256 threads (8 warps 2x4, warp tile 64x32),
// 4-stage cp.async, 2 CTAs/SM. A smem [m][k16], Bt smem [n][k16], swizzled.
// SCATTER=1: round + scatter q/k into [bh][t][d], v into [bh][d][t].
// ---------------------------------------------------------------------------
#define BM 128
#define BN 128
#define BK 16
#define STG 4
#define ASZ (BM * BK)
#define BSZ (BN * BK)
#define GEMM_SMEM (STG * (ASZ + BSZ) * 4)   // 65536 B

template <int SCATTER>
__global__ void __launch_bounds__(256, 2) gemm_tc(
    const float* __restrict__ A, const float* __restrict__ Bt,
    float* __restrict__ C, int M, int N, int K)
{
    extern __shared__ float sh[];
    float* As = sh;
    float* Bs = sh + STG * ASZ;

    const int tid  = threadIdx.x;
    const int lane = tid & 31;
    const int w    = tid >> 5;
    const int wm   = w >> 2;          // 0..1 -> m*64
    const int wn   = w & 3;           // 0..3 -> n*32
    const int g    = lane >> 2;
    const int cq   = lane & 3;
    const int sub  = lane >> 3;       // 0..3 (ldmatrix sub-matrix)
    const int rl   = lane & 7;
    const int bm   = blockIdx.y << 7;
    const int bn   = blockIdx.x << 7;

    const int NIT = K >> 4;

    auto load_tile = [&](int kt, int s) {
        const float* Ag = A + (size_t)bm * K + kt * BK;
#pragma unroll
        for (int i = 0; i < 2; i++) {
            int idx = tid + i * 256;
            int r = idx >> 2, c = idx & 3;
            cp16(&As[s * ASZ + r * 16 + SWG(r, c) * 4], Ag + (size_t)r * K + c * 4);
        }
        const float* Bg = Bt + (size_t)bn * K + kt * BK;
#pragma unroll
        for (int i = 0; i < 2; i++) {
            int idx = tid + i * 256;
            int r = idx >> 2, c = idx & 3;
            cp16(&Bs[s * BSZ + r * 16 + SWG(r, c) * 4], Bg + (size_t)r * K + c * 4);
        }
    };

    float acc[4][4][4];
#pragma unroll
    for (int mi = 0; mi < 4; mi++)
#pragma unroll
        for (int ni = 0; ni < 4; ni++)
#pragma unroll
            for (int r = 0; r < 4; r++) acc[mi][ni][r] = 0.0f;

#pragma unroll
    for (int s = 0; s < STG - 1; s++) { load_tile(s, s); CPCOMMIT(); }

#pragma unroll 1
    for (int kt = 0; kt < NIT; kt++) {
        asm volatile("cp.async.wait_group 2;");
        __syncthreads();

        if (kt + STG - 1 < NIT) load_tile(kt + STG - 1, (kt + STG - 1) & 3);
        CPCOMMIT();

        const float* Asb = As + (kt & 3) * ASZ;
        const float* Bsb = Bs + (kt & 3) * BSZ;

#pragma unroll
        for (int ks = 0; ks < 2; ks++) {
            const int chunk = ks * 2 + (sub >> 1);
            unsigned af[4][4], bf[2][4];
#pragma unroll
            for (int mi = 0; mi < 4; mi++) {
                const int row = wm * 64 + mi * 16 + (sub & 1) * 8 + rl;
                ldsm4(af[mi], Asb + row * 16 + SWG(row, chunk) * 4);
            }
#pragma unroll
            for (int p = 0; p < 2; p++) {
                const int row = wn * 32 + p * 16 + (sub & 1) * 8 + rl;
                ldsm4(bf[p], Bsb + row * 16 + SWG(row, chunk) * 4);
            }
#pragma unroll
            for (int mi = 0; mi < 4; mi++)
#pragma unroll
                for (int p = 0; p < 2; p++) {
                    mma_tf32(acc[mi][2 * p],     af[mi], bf[p][0], bf[p][2]);
                    mma_tf32(acc[mi][2 * p + 1], af[mi], bf[p][1], bf[p][3]);
                }
        }
    }

    // epilogue
#pragma unroll
    for (int mi = 0; mi < 4; mi++) {
        const int row = bm + wm * 64 + mi * 16 + g;
#pragma unroll
        for (int ni = 0; ni < 4; ni++) {
            const int col = bn + wn * 32 + ni * 8 + 2 * cq;
            if (SCATTER) {
                const int which = col >> 10;
                const int h     = (col & 1023) >> 6;
                const int d0    = col & 63;
                const int b     = row >> 11, t = row & 2047;
                if (which == 2) {
                    // V transposed: g_v[bh][d][t]
                    float* p = g_v + ((size_t)((b * 16 + h) * 64 + d0) << 11) + t;
                    p[0]            = rtf(acc[mi][ni][0]);
                    p[2048]         = rtf(acc[mi][ni][1]);
                    p[8]            = rtf(acc[mi][ni][2]);
                    p[2048 + 8]     = rtf(acc[mi][ni][3]);
                } else {
                    float* dst = (which == 0) ? g_q : g_k;
                    float* p = dst + ((size_t)((b * 16 + h) * 2048 + t) << 6) + d0;
                    *(float2*)p = make_float2(rtf(acc[mi][ni][0]), rtf(acc[mi][ni][1]));
                    *(float2*)(p + (8 << 6)) =
                        make_float2(rtf(acc[mi][ni][2]), rtf(acc[mi][ni][3]));
                }
            } else {
                *(float2*)&C[(size_t)row * N + col] =
                    make_float2(acc[mi][ni][0], acc[mi][ni][1]);
                *(float2*)&C[(size_t)(row + 8) * N + col] =
                    make_float2(acc[mi][ni][2], acc[mi][ni][3]);
            }
        }
    }
}

// ---------------------------------------------------------------------------
// Causal flash attention, 256 threads = 8 warps, 128 q rows/block.
// All fragments via ldmatrix. K/V double-buffered cp.async. V is [d][t].
// smem rows are 64 floats, swizzle SWA.
// ---------------------------------------------------------------------------
#define AQ  (128 * 64)
#define AKV (64 * 64)
#define ATTN_SMEM ((AQ + 4 * AKV + 128 * 64) * 4)   // 131072 B
#define SCL 0.180336880f   // 0.125 * log2(e)

__global__ void __launch_bounds__(256, 1) attn_tc()
{
    extern __shared__ float sh[];
    float* Qs = sh;                    // [128][64]
    float* Ks = sh + AQ;               // [2][64][64]  (rows = kpos)
    float* Vs = sh + AQ + 2 * AKV;     // [2][64][64]  (rows = d)
    float* Ps = sh + AQ + 4 * AKV;     // [128][64]

    const int tid  = threadIdx.x;
    const int lane = tid & 31;
    const int w    = tid >> 5;
    const int g    = lane >> 2;
    const int cq   = lane & 3;
    const int sub  = lane >> 3;
    const int rl   = lane & 7;
    const int bh   = blockIdx.y;
    const int q0   = blockIdx.x << 7;

    const float* Qg  = g_q + ((size_t)bh * NT + q0) * ND;
    const float* Kg0 = g_k + (size_t)bh * NT * ND;
    const float* Vg0 = g_v + (size_t)bh * ND * NT;   // [d][t]

    auto load_kv = [&](int kt, int s) {
        const float* Kg = Kg0 + ((size_t)kt << 12);
        const float* Vg = Vg0 + (kt << 6);
#pragma unroll
        for (int i = 0; i < 4; i++) {
            int idx = tid + i * 256;
            int r = idx >> 4, c = idx & 15;
            cp16(&Ks[s * AKV + r * 64 + SWA(r, c) * 4], Kg + r * 64 + c * 4);
            cp16(&Vs[s * AKV + r * 64 + SWA(r, c) * 4], Vg + (size_t)r * NT + c * 4);
        }
    };

#pragma unroll
    for (int i = 0; i < 8; i++) {
        int idx = tid + i * 256;
        int r = idx >> 4, c = idx & 15;
        cp16(&Qs[r * 64 + SWA(r, c) * 4], Qg + r * 64 + c * 4);
    }
    load_kv(0, 0);
    CPCOMMIT();

    float m0 = -1e30f, m1 = -1e30f, l0 = 0.0f, l1 = 0.0f;
    float o[8][4];
#pragma unroll
    for (int nt = 0; nt < 8; nt++)
#pragma unroll
        for (int r = 0; r < 4; r++) o[nt][r] = 0.0f;

    const int rq    = w * 16 + g;
    const int rowA  = w * 16 + (sub & 1) * 8 + rl;   // ldmatrix A row
    const int ktmax = (q0 >> 6) + 1;

    for (int kt = 0; kt <= ktmax; kt++) {
        asm volatile("cp.async.wait_group 0;");
        __syncthreads();

        if (kt < ktmax) load_kv(kt + 1, (kt + 1) & 1);
        CPCOMMIT();

        if (kt * 64 <= q0 + w * 16 + 15) {
            const float* Kb = Ks + (kt & 1) * AKV;
            const float* Vb = Vs + (kt & 1) * AKV;

            float s[8][4];
#pragma unroll
            for (int nt = 0; nt < 8; nt++)
#pragma unroll
                for (int r = 0; r < 4; r++) s[nt][r] = 0.0f;

            // S = Q K^T
#pragma unroll
            for (int ks = 0; ks < 8; ks++) {
                const int chunk = ks * 2 + (sub >> 1);
                unsigned aq[4];
                ldsm4(aq, Qs + rowA * 64 + SWA(rowA, chunk) * 4);
#pragma unroll
                for (int p = 0; p < 4; p++) {
                    const int rk = p * 16 + (sub & 1) * 8 + rl;
                    unsigned bk[4];
                    ldsm4(bk, Kb + rk * 64 + SWA(rk, chunk) * 4);
                    mma_tf32(s[2 * p],     aq, bk[0], bk[2]);
                    mma_tf32(s[2 * p + 1], aq, bk[1], bk[3]);
                }
            }

#pragma unroll
            for (int nt = 0; nt < 8; nt++)
#pragma unroll
                for (int r = 0; r < 4; r++) s[nt][r] *= SCL;

            if (kt * 64 + 63 > q0 + w * 16) {   // diagonal tile: mask
                const int r0 = q0 + rq, r1 = q0 + rq + 8;
#pragma unroll
                for (int nt = 0; nt < 8; nt++) {
                    int gc = kt * 64 + nt * 8 + 2 * cq;
                    if (gc     > r0) s[nt][0] = -1e30f;
                    if (gc + 1 > r0) s[nt][1] = -1e30f;
                    if (gc     > r1) s[nt][2] = -1e30f;
                    if (gc + 1 > r1) s[nt][3] = -1e30f;
                }
            }

            // online softmax (log2 domain)
            float rm0 = -1e30f, rm1 = -1e30f;
#pragma unroll
            for (int nt = 0; nt < 8; nt++) {
                rm0 = fmaxf(rm0, fmaxf(s[nt][0], s[nt][1]));
                rm1 = fmaxf(rm1, fmaxf(s[nt][2], s[nt][3]));
            }
            rm0 = fmaxf(rm0, __shfl_xor_sync(0xffffffffu, rm0, 1));
            rm0 = fmaxf(rm0, __shfl_xor_sync(0xffffffffu, rm0, 2));
            rm1 = fmaxf(rm1, __shfl_xor_sync(0xffffffffu, rm1, 1));
            rm1 = fmaxf(rm1, __shfl_xor_sync(0xffffffffu, rm1, 2));

            float mn0 = fmaxf(m0, rm0), mn1 = fmaxf(m1, rm1);
            float sc0 = fexp2(m0 - mn0), sc1 = fexp2(m1 - mn1);
            float rs0 = 0.0f, rs1 = 0.0f;
#pragma unroll
            for (int nt = 0; nt < 8; nt++) {
                s[nt][0] = fexp2(s[nt][0] - mn0);
                s[nt][1] = fexp2(s[nt][1] - mn0);
                s[nt][2] = fexp2(s[nt][2] - mn1);
                s[nt][3] = fexp2(s[nt][3] - mn1);
                rs0 += s[nt][0] + s[nt][1];
                rs1 += s[nt][2] + s[nt][3];
            }
            rs0 += __shfl_xor_sync(0xffffffffu, rs0, 1);
            rs0 += __shfl_xor_sync(0xffffffffu, rs0, 2);
            rs1 += __shfl_xor_sync(0xffffffffu, rs1, 1);
            rs1 += __shfl_xor_sync(0xffffffffu, rs1, 2);
            l0 = l0 * sc0 + rs0;
            l1 = l1 * sc1 + rs1;
            m0 = mn0; m1 = mn1;
#pragma unroll
            for (int nt = 0; nt < 8; nt++) {
                o[nt][0] *= sc0; o[nt][1] *= sc0;
                o[nt][2] *= sc1; o[nt][3] *= sc1;
            }

            // P -> smem (warp-private rows), swizzled, rounded
#pragma unroll
            for (int nt = 0; nt < 8; nt++) {
                const int ch = nt * 2 + (cq >> 1);
                const int of = (2 * cq) & 3;
                *(float2*)&Ps[rq * 64 + SWA(rq, ch) * 4 + of] =
                    make_float2(rtf(s[nt][0]), rtf(s[nt][1]));
                *(float2*)&Ps[(rq + 8) * 64 + SWA(rq + 8, ch) * 4 + of] =
                    make_float2(rtf(s[nt][2]), rtf(s[nt][3]));
            }
            __syncwarp();

            // O += P V   (V is [d][t] in smem: rows = d)
#pragma unroll
            for (int ks = 0; ks < 8; ks++) {
                const int chunk = ks * 2 + (sub >> 1);
                unsigned ap[4];
                ldsm4(ap, Ps + rowA * 64 + SWA(rowA, chunk) * 4);
#pragma unroll
                for (int p = 0; p < 4; p++) {
                    const int rv = p * 16 + (sub & 1) * 8 + rl;   // d row
                    unsigned bv[4];
                    ldsm4(bv, Vb + rv * 64 + SWA(rv, chunk) * 4);
                    mma_tf32(o[2 * p],     ap, bv[0], bv[2]);
                    mma_tf32(o[2 * p + 1], ap, bv[1], bv[3]);
                }
            }
            __syncwarp();
        }
    }

    const int b = bh >> 4;
    const int h = bh & 15;
    const float inv0 = 1.0f / l0;
    const float inv1 = 1.0f / l1;
    float* Og = g_att + ((size_t)(b * NT + q0 + rq)) * NC + (h << 6);
#pragma unroll
    for (int nt = 0; nt < 8; nt++) {
        int col = nt * 8 + 2 * cq;
        *(float2*)(Og + col) =
            make_float2(rtf(o[nt][0] * inv0), rtf(o[nt][1] * inv0));
        *(float2*)(Og + (size_t)8 * NC + col) =
            make_float2(rtf(o[nt][2] * inv1), rtf(o[nt][3] * inv1));
    }
}

// ---------------------------------------------------------------------------
// launch
// ---------------------------------------------------------------------------
extern "C" void kernel_launch(void* const* d_in, const int* in_sizes, int n_in,
                              void* d_out, int out_size)
{
    const float* x     = (const float*)d_in[0];
    const float* Wqkv  = (const float*)d_in[1];
    const float* Wproj = (const float*)d_in[2];
    float* out = (float*)d_out;

    void *px, *pwqkv, *pwproj, *patt;
    cudaGetSymbolAddress(&px, g_x);
    cudaGetSymbolAddress(&pwqkv, g_wqkv);
    cudaGetSymbolAddress(&pwproj, g_wproj);
    cudaGetSymbolAddress(&patt, g_att);

    cudaFuncSetAttribute(gemm_tc<1>,
                         cudaFuncAttributeMaxDynamicSharedMemorySize, GEMM_SMEM);
    cudaFuncSetAttribute(gemm_tc<0>,
                         cudaFuncAttributeMaxDynamicSharedMemorySize, GEMM_SMEM);
    cudaFuncSetAttribute(attn_tc,
                         cudaFuncAttributeMaxDynamicSharedMemorySize, ATTN_SMEM);

    // 0) pre-round x; round+transpose weights to [n][k]
    cvt_kernel<<<(NM * NC / 4 + 255) / 256, 256>>>(
        (const float4*)x, (uint4*)px, NM * NC / 4);
    cvt_t_kernel<<<dim3(3 * NC / 32, NC / 32), 256>>>(
        Wqkv, (float*)pwqkv, NC, 3 * NC);
    cvt_t_kernel<<<dim3(NC / 32, NC / 32), 256>>>(
        Wproj, (float*)pwproj, NC, NC);

    // 1) qkv = x @ Wqkv -> scatter q,k [bh][t][d], v [bh][d][t]
    gemm_tc<1><<<dim3(3 * NC / BN, NM / BM), 256, GEMM_SMEM>>>(
        (const float*)px, (const float*)pwqkv, nullptr, NM, 3 * NC, NC);

    // 2) causal attention -> g_att (rounded)
    attn_tc<<<dim3(NT / 128, NBH), 256, ATTN_SMEM>>>();

    // 3) out = g_att @ Wproj
    gemm_tc<0><<<dim3(NC / BN, NM / BM), 256, GEMM_SMEM>>>(
        (const float*)patt, (const float*)pwproj, out, NM, NC, NC);
}

// round 7
// speedup vs baseline: 3.8081x; 1.0846x over previous
#include <cuda_runtime.h>

// ---------------------------------------------------------------------------
// B=4, T=2048, C=1024, H=16, D=64.  All matmuls: mma.sync.m16n8k8.tf32.
// ldmatrix fragments, cp.async pipelines, pre-rounded tf32 inputs.
// GEMM: BK=32, 3 stages, 2 CTAs/SM.  Attention: 64-q blocks, 2 CTAs/SM.
// ---------------------------------------------------------------------------

#define NBH 64
#define NT  2048
#define ND  64
#define NC  1024
#define NM  8192

__device__ float g_q[NBH * NT * ND];
__device__ float g_k[NBH * NT * ND];
__device__ float g_v[NBH * NT * ND];        // transposed: [bh][d][t]
__device__ float g_att[NM * NC];
__device__ float g_x[NM * NC];
__device__ float g_wqkv[3 * NC * NC];       // transposed: [n][k]
__device__ float g_wproj[NC * NC];          // transposed: [n][k]

__device__ __forceinline__ unsigned f2tf(float f) {
    unsigned u;
    asm("cvt.rna.tf32.f32 %0, %1;" : "=r"(u) : "f"(f));
    return u;
}
__device__ __forceinline__ float rtf(float x) { return __uint_as_float(f2tf(x)); }

__device__ __forceinline__ void mma_tf32(float* c, const unsigned* a,
                                         unsigned b0, unsigned b1) {
    asm volatile(
        "mma.sync.aligned.m16n8k8.row.col.f32.tf32.tf32.f32 "
        "{%0,%1,%2,%3}, {%4,%5,%6,%7}, {%8,%9}, {%0,%1,%2,%3};"
        : "+f"(c[0]), "+f"(c[1]), "+f"(c[2]), "+f"(c[3])
        : "r"(a[0]), "r"(a[1]), "r"(a[2]), "r"(a[3]), "r"(b0), "r"(b1));
}

__device__ __forceinline__ void ldsm4(unsigned* r, const float* p) {
    unsigned a = (unsigned)__cvta_generic_to_shared(p);
    asm volatile("ldmatrix.sync.aligned.m8n8.x4.shared.b16 {%0,%1,%2,%3}, [%4];"
                 : "=r"(r[0]), "=r"(r[1]), "=r"(r[2]), "=r"(r[3]) : "r"(a));
}

__device__ __forceinline__ void cp16(void* smem_dst, const void* gmem_src) {
    unsigned sa = (unsigned)__cvta_generic_to_shared(smem_dst);
    asm volatile("cp.async.cg.shared.global [%0], [%1], 16;" :: "r"(sa), "l"(gmem_src));
}
#define CPCOMMIT() asm volatile("cp.async.commit_group;")

__device__ __forceinline__ float fexp2(float x) {
    float y;
    asm("ex2.approx.f32 %0, %1;" : "=f"(y) : "f"(x));
    return y;
}

// swizzles (chunk = 4-float group within a row)
#define SWB(r, c) ((c) ^ ((r) & 7))          // rows of 32 floats (GEMM BK=32)
#define SWA(r, c) ((c) ^ ((r) & 7))          // rows of 64 floats (attention)

// ---------------------------------------------------------------------------
// pre-round kernels
// ---------------------------------------------------------------------------
__global__ void cvt_kernel(const float4* __restrict__ src,
                           uint4* __restrict__ dst, int n4)
{
    int i = blockIdx.x * 256 + threadIdx.x;
    if (i < n4) {
        float4 v = src[i];
        uint4 u;
        u.x = f2tf(v.x); u.y = f2tf(v.y); u.z = f2tf(v.z); u.w = f2tf(v.w);
        dst[i] = u;
    }
}

// round + transpose W[K][N] -> Wt[N][K]
__global__ void cvt_t_kernel(const float* __restrict__ src,
                             float* __restrict__ dst, int K, int N)
{
    __shared__ float t[32][33];
    const int n0 = blockIdx.x << 5;
    const int k0 = blockIdx.y << 5;
    const int tx = threadIdx.x & 31;
    const int ty = threadIdx.x >> 5;   // 0..7
#pragma unroll
    for (int j = 0; j < 4; j++)
        t[ty + j * 8][tx] = src[(size_t)(k0 + ty + j * 8) * N + n0 + tx];
    __syncthreads();
#pragma unroll
    for (int j = 0; j < 4; j++)
        dst[(size_t)(n0 + ty + j * 8) * K + k0 + tx] = rtf(t[tx][ty + j * 8]);
}

// ---------------------------------------------------------------------------
// GEMM: 128m x 128n x 32k tile, 256 threads (8 warps 2x4, warp tile 64x32),
// 3-stage cp.async, 2 CTAs/SM. A smem [m][k32], Bt smem [n][k32], swizzled.
// SCATTER=1: round + scatter q/k into [bh][t][d], v into [bh][d][t].
// ---------------------------------------------------------------------------
#define BM 128
#define BN 128
#define BK 32
#define STG 3
#define ASZ (BM * BK)
#define BSZ (BN * BK)
#define GEMM_SMEM (STG * (ASZ + BSZ) * 4)   // 98304 B

template <int SCATTER>
__global__ void __launch_bounds__(256, 2) gemm_tc(
    const float* __restrict__ A, const float* __restrict__ Bt,
    float* __restrict__ C, int M, int N, int K)
{
    extern __shared__ float sh[];
    float* As = sh;
    float* Bs = sh + STG * ASZ;

    const int tid  = threadIdx.x;
    const int lane = tid & 31;
    const int w    = tid >> 5;
    const int wm   = w >> 2;          // 0..1 -> m*64
    const int wn   = w & 3;           // 0..3 -> n*32
    const int g    = lane >> 2;
    const int cq   = lane & 3;
    const int sub  = lane >> 3;       // 0..3 (ldmatrix sub-matrix)
    const int rl   = lane & 7;
    const int bm   = blockIdx.y << 7;
    const int bn   = blockIdx.x << 7;

    const int NIT = K >> 5;

    auto load_tile = [&](int kt, int s) {
        const float* Ag = A + (size_t)bm * K + kt * BK;
#pragma unroll
        for (int i = 0; i < 4; i++) {
            int idx = tid + i * 256;
            int r = idx >> 3, c = idx & 7;
            cp16(&As[s * ASZ + r * 32 + SWB(r, c) * 4], Ag + (size_t)r * K + c * 4);
        }
        const float* Bg = Bt + (size_t)bn * K + kt * BK;
#pragma unroll
        for (int i = 0; i < 4; i++) {
            int idx = tid + i * 256;
            int r = idx >> 3, c = idx & 7;
            cp16(&Bs[s * BSZ + r * 32 + SWB(r, c) * 4], Bg + (size_t)r * K + c * 4);
        }
    };

    float acc[4][4][4];
#pragma unroll
    for (int mi = 0; mi < 4; mi++)
#pragma unroll
        for (int ni = 0; ni < 4; ni++)
#pragma unroll
            for (int r = 0; r < 4; r++) acc[mi][ni][r] = 0.0f;

    load_tile(0, 0); CPCOMMIT();
    load_tile(1, 1); CPCOMMIT();

    int s_cur = 0, s_nxt = 2;
#pragma unroll 1
    for (int kt = 0; kt < NIT; kt++) {
        asm volatile("cp.async.wait_group 1;");
        __syncthreads();

        if (kt + 2 < NIT) load_tile(kt + 2, s_nxt);
        CPCOMMIT();

        const float* Asb = As + s_cur * ASZ;
        const float* Bsb = Bs + s_cur * BSZ;
        s_nxt = s_cur;
        s_cur = (s_cur == 2) ? 0 : s_cur + 1;

#pragma unroll
        for (int ks = 0; ks < 4; ks++) {
            const int chunk = ks * 2 + (sub >> 1);
            unsigned af[4][4], bf[2][4];
#pragma unroll
            for (int mi = 0; mi < 4; mi++) {
                const int row = wm * 64 + mi * 16 + (sub & 1) * 8 + rl;
                ldsm4(af[mi], Asb + row * 32 + SWB(row, chunk) * 4);
            }
#pragma unroll
            for (int p = 0; p < 2; p++) {
                const int row = wn * 32 + p * 16 + (sub & 1) * 8 + rl;
                ldsm4(bf[p], Bsb + row * 32 + SWB(row, chunk) * 4);
            }
#pragma unroll
            for (int mi = 0; mi < 4; mi++)
#pragma unroll
                for (int p = 0; p < 2; p++) {
                    mma_tf32(acc[mi][2 * p],     af[mi], bf[p][0], bf[p][2]);
                    mma_tf32(acc[mi][2 * p + 1], af[mi], bf[p][1], bf[p][3]);
                }
        }
    }

    // epilogue
#pragma unroll
    for (int mi = 0; mi < 4; mi++) {
        const int row = bm + wm * 64 + mi * 16 + g;
#pragma unroll
        for (int ni = 0; ni < 4; ni++) {
            const int col = bn + wn * 32 + ni * 8 + 2 * cq;
            if (SCATTER) {
                const int which = col >> 10;
                const int h     = (col & 1023) >> 6;
                const int d0    = col & 63;
                const int b     = row >> 11, t = row & 2047;
                if (which == 2) {
                    // V transposed: g_v[bh][d][t]
                    float* p = g_v + ((size_t)((b * 16 + h) * 64 + d0) << 11) + t;
                    p[0]            = rtf(acc[mi][ni][0]);
                    p[2048]         = rtf(acc[mi][ni][1]);
                    p[8]            = rtf(acc[mi][ni][2]);
                    p[2048 + 8]     = rtf(acc[mi][ni][3]);
                } else {
                    float* dst = (which == 0) ? g_q : g_k;
                    float* p = dst + ((size_t)((b * 16 + h) * 2048 + t) << 6) + d0;
                    *(float2*)p = make_float2(rtf(acc[mi][ni][0]), rtf(acc[mi][ni][1]));
                    *(float2*)(p + (8 << 6)) =
                        make_float2(rtf(acc[mi][ni][2]), rtf(acc[mi][ni][3]));
                }
            } else {
                *(float2*)&C[(size_t)row * N + col] =
                    make_float2(acc[mi][ni][0], acc[mi][ni][1]);
                *(float2*)&C[(size_t)(row + 8) * N + col] =
                    make_float2(acc[mi][ni][2], acc[mi][ni][3]);
            }
        }
    }
}

// ---------------------------------------------------------------------------
// Causal flash attention, 128 threads = 4 warps, 64 q rows/block, 2 CTAs/SM.
// All fragments via ldmatrix. K/V double-buffered cp.async. V is [d][t].
// smem rows are 64 floats, swizzle SWA. 96 KB smem.
// ---------------------------------------------------------------------------
#define AQ  (64 * 64)
#define AKV (64 * 64)
#define ATTN_SMEM ((AQ + 4 * AKV + 64 * 64) * 4)   // 98304 B
#define SCL 0.180336880f   // 0.125 * log2(e)

__global__ void __launch_bounds__(128, 2) attn_tc()
{
    extern __shared__ float sh[];
    float* Qs = sh;                    // [64][64]
    float* Ks = sh + AQ;               // [2][64][64]  (rows = kpos)
    float* Vs = sh + AQ + 2 * AKV;     // [2][64][64]  (rows = d)
    float* Ps = sh + AQ + 4 * AKV;     // [64][64]

    const int tid  = threadIdx.x;
    const int lane = tid & 31;
    const int w    = tid >> 5;         // 0..3
    const int g    = lane >> 2;
    const int cq   = lane & 3;
    const int sub  = lane >> 3;
    const int rl   = lane & 7;
    const int bh   = blockIdx.y;
    const int q0   = blockIdx.x << 6;

    const float* Qg  = g_q + ((size_t)bh * NT + q0) * ND;
    const float* Kg0 = g_k + (size_t)bh * NT * ND;
    const float* Vg0 = g_v + (size_t)bh * ND * NT;   // [d][t]

    auto load_kv = [&](int kt, int s) {
        const float* Kg = Kg0 + ((size_t)kt << 12);
        const float* Vg = Vg0 + (kt << 6);
#pragma unroll
        for (int i = 0; i < 8; i++) {
            int idx = tid + i * 128;
            int r = idx >> 4, c = idx & 15;
            cp16(&Ks[s * AKV + r * 64 + SWA(r, c) * 4], Kg + r * 64 + c * 4);
            cp16(&Vs[s * AKV + r * 64 + SWA(r, c) * 4], Vg + (size_t)r * NT + c * 4);
        }
    };

#pragma unroll
    for (int i = 0; i < 8; i++) {
        int idx = tid + i * 128;
        int r = idx >> 4, c = idx & 15;
        cp16(&Qs[r * 64 + SWA(r, c) * 4], Qg + r * 64 + c * 4);
    }
    load_kv(0, 0);
    CPCOMMIT();

    float m0 = -1e30f, m1 = -1e30f, l0 = 0.0f, l1 = 0.0f;
    float o[8][4];
#pragma unroll
    for (int nt = 0; nt < 8; nt++)
#pragma unroll
        for (int r = 0; r < 4; r++) o[nt][r] = 0.0f;

    const int rq    = w * 16 + g;
    const int rowA  = w * 16 + (sub & 1) * 8 + rl;   // ldmatrix A row
    const int ktmax = q0 >> 6;

    for (int kt = 0; kt <= ktmax; kt++) {
        asm volatile("cp.async.wait_group 0;");
        __syncthreads();

        if (kt < ktmax) load_kv(kt + 1, (kt + 1) & 1);
        CPCOMMIT();

        const float* Kb = Ks + (kt & 1) * AKV;
        const float* Vb = Vs + (kt & 1) * AKV;

        float s[8][4];
#pragma unroll
        for (int nt = 0; nt < 8; nt++)
#pragma unroll
            for (int r = 0; r < 4; r++) s[nt][r] = 0.0f;

        // S = Q K^T
#pragma unroll
        for (int ks = 0; ks < 8; ks++) {
            const int chunk = ks * 2 + (sub >> 1);
            unsigned aq[4];
            ldsm4(aq, Qs + rowA * 64 + SWA(rowA, chunk) * 4);
#pragma unroll
            for (int p = 0; p < 4; p++) {
                const int rk = p * 16 + (sub & 1) * 8 + rl;
                unsigned bk[4];
                ldsm4(bk, Kb + rk * 64 + SWA(rk, chunk) * 4);
                mma_tf32(s[2 * p],     aq, bk[0], bk[2]);
                mma_tf32(s[2 * p + 1], aq, bk[1], bk[3]);
            }
        }

#pragma unroll
        for (int nt = 0; nt < 8; nt++)
#pragma unroll
            for (int r = 0; r < 4; r++) s[nt][r] *= SCL;

        if (kt == ktmax) {   // diagonal tile: mask
            const int r0 = rq, r1 = rq + 8;
#pragma unroll
            for (int nt = 0; nt < 8; nt++) {
                int gc = nt * 8 + 2 * cq;
                if (gc     > r0) s[nt][0] = -1e30f;
                if (gc + 1 > r0) s[nt][1] = -1e30f;
                if (gc     > r1) s[nt][2] = -1e30f;
                if (gc + 1 > r1) s[nt][3] = -1e30f;
            }
        }

        // online softmax (log2 domain)
        float rm0 = -1e30f, rm1 = -1e30f;
#pragma unroll
        for (int nt = 0; nt < 8; nt++) {
            rm0 = fmaxf(rm0, fmaxf(s[nt][0], s[nt][1]));
            rm1 = fmaxf(rm1, fmaxf(s[nt][2], s[nt][3]));
        }
        rm0 = fmaxf(rm0, __shfl_xor_sync(0xffffffffu, rm0, 1));
        rm0 = fmaxf(rm0, __shfl_xor_sync(0xffffffffu, rm0, 2));
        rm1 = fmaxf(rm1, __shfl_xor_sync(0xffffffffu, rm1, 1));
        rm1 = fmaxf(rm1, __shfl_xor_sync(0xffffffffu, rm1, 2));

        float mn0 = fmaxf(m0, rm0), mn1 = fmaxf(m1, rm1);
        float sc0 = fexp2(m0 - mn0), sc1 = fexp2(m1 - mn1);
        float rs0 = 0.0f, rs1 = 0.0f;
#pragma unroll
        for (int nt = 0; nt < 8; nt++) {
            s[nt][0] = fexp2(s[nt][0] - mn0);
            s[nt][1] = fexp2(s[nt][1] - mn0);
            s[nt][2] = fexp2(s[nt][2] - mn1);
            s[nt][3] = fexp2(s[nt][3] - mn1);
            rs0 += s[nt][0] + s[nt][1];
            rs1 += s[nt][2] + s[nt][3];
        }
        rs0 += __shfl_xor_sync(0xffffffffu, rs0, 1);
        rs0 += __shfl_xor_sync(0xffffffffu, rs0, 2);
        rs1 += __shfl_xor_sync(0xffffffffu, rs1, 1);
        rs1 += __shfl_xor_sync(0xffffffffu, rs1, 2);
        l0 = l0 * sc0 + rs0;
        l1 = l1 * sc1 + rs1;
        m0 = mn0; m1 = mn1;
#pragma unroll
        for (int nt = 0; nt < 8; nt++) {
            o[nt][0] *= sc0; o[nt][1] *= sc0;
            o[nt][2] *= sc1; o[nt][3] *= sc1;
        }

        // P -> smem (warp-private rows), swizzled, rounded
#pragma unroll
        for (int nt = 0; nt < 8; nt++) {
            const int ch = nt * 2 + (cq >> 1);
            const int of = (2 * cq) & 3;
            *(float2*)&Ps[rq * 64 + SWA(rq, ch) * 4 + of] =
                make_float2(rtf(s[nt][0]), rtf(s[nt][1]));
            *(float2*)&Ps[(rq + 8) * 64 + SWA(rq + 8, ch) * 4 + of] =
                make_float2(rtf(s[nt][2]), rtf(s[nt][3]));
        }
        __syncwarp();

        // O += P V   (V is [d][t] in smem: rows = d)
#pragma unroll
        for (int ks = 0; ks < 8; ks++) {
            const int chunk = ks * 2 + (sub >> 1);
            unsigned ap[4];
            ldsm4(ap, Ps + rowA * 64 + SWA(rowA, chunk) * 4);
#pragma unroll
            for (int p = 0; p < 4; p++) {
                const int rv = p * 16 + (sub & 1) * 8 + rl;   // d row
                unsigned bv[4];
                ldsm4(bv, Vb + rv * 64 + SWA(rv, chunk) * 4);
                mma_tf32(o[2 * p],     ap, bv[0], bv[2]);
                mma_tf32(o[2 * p + 1], ap, bv[1], bv[3]);
            }
        }
        __syncwarp();
    }

    const int b = bh >> 4;
    const int h = bh & 15;
    const float inv0 = 1.0f / l0;
    const float inv1 = 1.0f / l1;
    float* Og = g_att + ((size_t)(b * NT + q0 + rq)) * NC + (h << 6);
#pragma unroll
    for (int nt = 0; nt < 8; nt++) {
        int col = nt * 8 + 2 * cq;
        *(float2*)(Og + col) =
            make_float2(rtf(o[nt][0] * inv0), rtf(o[nt][1] * inv0));
        *(float2*)(Og + (size_t)8 * NC + col) =
            make_float2(rtf(o[nt][2] * inv1), rtf(o[nt][3] * inv1));
    }
}

// ---------------------------------------------------------------------------
// launch
// ---------------------------------------------------------------------------
extern "C" void kernel_launch(void* const* d_in, const int* in_sizes, int n_in,
                              void* d_out, int out_size)
{
    const float* x     = (const float*)d_in[0];
    const float* Wqkv  = (const float*)d_in[1];
    const float* Wproj = (const float*)d_in[2];
    float* out = (float*)d_out;

    void *px, *pwqkv, *pwproj, *patt;
    cudaGetSymbolAddress(&px, g_x);
    cudaGetSymbolAddress(&pwqkv, g_wqkv);
    cudaGetSymbolAddress(&pwproj, g_wproj);
    cudaGetSymbolAddress(&patt, g_att);

    cudaFuncSetAttribute(gemm_tc<1>,
                         cudaFuncAttributeMaxDynamicSharedMemorySize, GEMM_SMEM);
    cudaFuncSetAttribute(gemm_tc<0>,
                         cudaFuncAttributeMaxDynamicSharedMemorySize, GEMM_SMEM);
    cudaFuncSetAttribute(attn_tc,
                         cudaFuncAttributeMaxDynamicSharedMemorySize, ATTN_SMEM);

    // 0) pre-round x; round+transpose weights to [n][k]
    cvt_kernel<<<(NM * NC / 4 + 255) / 256, 256>>>(
        (const float4*)x, (uint4*)px, NM * NC / 4);
    cvt_t_kernel<<<dim3(3 * NC / 32, NC / 32), 256>>>(
        Wqkv, (float*)pwqkv, NC, 3 * NC);
    cvt_t_kernel<<<dim3(NC / 32, NC / 32), 256>>>(
        Wproj, (float*)pwproj, NC, NC);

    // 1) qkv = x @ Wqkv -> scatter q,k [bh][t][d], v [bh][d][t]
    gemm_tc<1><<<dim3(3 * NC / BN, NM / BM), 256, GEMM_SMEM>>>(
        (const float*)px, (const float*)pwqkv, nullptr, NM, 3 * NC, NC);

    // 2) causal attention -> g_att (rounded)
    attn_tc<<<dim3(NT / 64, NBH), 128, ATTN_SMEM>>>();

    // 3) out = g_att @ Wproj
    gemm_tc<0><<<dim3(NC / BN, NM / BM), 256, GEMM_SMEM>>>(
        (const float*)patt, (const float*)pwproj, out, NM, NC, NC);
}

// round 9
// speedup vs baseline: 3.8281x; 1.0053x over previous
#include <cuda_runtime.h>

// ---------------------------------------------------------------------------
// B=4, T=2048, C=1024, H=16, D=64.  All matmuls: mma.sync.m16n8k8.tf32.
// ldmatrix fragments, cp.async pipelines, pre-rounded tf32 inputs.
// GEMM: 128x128x32 tile, 4 warps (64x64 warp tile), 3 stages, 2 CTAs/SM.
// Attention: 64-q blocks, 2 CTAs/SM, Q fragments hoisted to registers.
// ---------------------------------------------------------------------------

#define NBH 64
#define NT  2048
#define ND  64
#define NC  1024
#define NM  8192

__device__ float g_q[NBH * NT * ND];
__device__ float g_k[NBH * NT * ND];
__device__ float g_v[NBH * NT * ND];        // transposed: [bh][d][t]
__device__ float g_att[NM * NC];
__device__ float g_x[NM * NC];
__device__ float g_wqkv[3 * NC * NC];       // transposed: [n][k]
__device__ float g_wproj[NC * NC];          // transposed: [n][k]

__device__ __forceinline__ unsigned f2tf(float f) {
    unsigned u;
    asm("cvt.rna.tf32.f32 %0, %1;" : "=r"(u) : "f"(f));
    return u;
}
__device__ __forceinline__ float rtf(float x) { return __uint_as_float(f2tf(x)); }

__device__ __forceinline__ void mma_tf32(float* c, const unsigned* a,
                                         unsigned b0, unsigned b1) {
    asm volatile(
        "mma.sync.aligned.m16n8k8.row.col.f32.tf32.tf32.f32 "
        "{%0,%1,%2,%3}, {%4,%5,%6,%7}, {%8,%9}, {%0,%1,%2,%3};"
        : "+f"(c[0]), "+f"(c[1]), "+f"(c[2]), "+f"(c[3])
        : "r"(a[0]), "r"(a[1]), "r"(a[2]), "r"(a[3]), "r"(b0), "r"(b1));
}

__device__ __forceinline__ void ldsm4(unsigned* r, const float* p) {
    unsigned a = (unsigned)__cvta_generic_to_shared(p);
    asm volatile("ldmatrix.sync.aligned.m8n8.x4.shared.b16 {%0,%1,%2,%3}, [%4];"
                 : "=r"(r[0]), "=r"(r[1]), "=r"(r[2]), "=r"(r[3]) : "r"(a));
}

__device__ __forceinline__ void cp16(void* smem_dst, const void* gmem_src) {
    unsigned sa = (unsigned)__cvta_generic_to_shared(smem_dst);
    asm volatile("cp.async.cg.shared.global [%0], [%1], 16;" :: "r"(sa), "l"(gmem_src));
}
#define CPCOMMIT() asm volatile("cp.async.commit_group;")

__device__ __forceinline__ float fexp2(float x) {
    float y;
    asm("ex2.approx.f32 %0, %1;" : "=f"(y) : "f"(x));
    return y;
}

// swizzles (chunk = 4-float group within a row)
#define SWB(r, c) ((c) ^ ((r) & 7))          // rows of 32 floats (GEMM BK=32)
#define SWA(r, c) ((c) ^ ((r) & 7))          // rows of 64 floats (attention)

// ---------------------------------------------------------------------------
// pre-round kernels
// ---------------------------------------------------------------------------
__global__ void cvt_kernel(const float4* __restrict__ src,
                           uint4* __restrict__ dst, int n4)
{
    int i = blockIdx.x * 256 + threadIdx.x;
    if (i < n4) {
        float4 v = src[i];
        uint4 u;
        u.x = f2tf(v.x); u.y = f2tf(v.y); u.z = f2tf(v.z); u.w = f2tf(v.w);
        dst[i] = u;
    }
}

// round + transpose W[K][N] -> Wt[N][K]
__global__ void cvt_t_kernel(const float* __restrict__ src,
                             float* __restrict__ dst, int K, int N)
{
    __shared__ float t[32][33];
    const int n0 = blockIdx.x << 5;
    const int k0 = blockIdx.y << 5;
    const int tx = threadIdx.x & 31;
    const int ty = threadIdx.x >> 5;   // 0..7
#pragma unroll
    for (int j = 0; j < 4; j++)
        t[ty + j * 8][tx] = src[(size_t)(k0 + ty + j * 8) * N + n0 + tx];
    __syncthreads();
#pragma unroll
    for (int j = 0; j < 4; j++)
        dst[(size_t)(n0 + ty + j * 8) * K + k0 + tx] = rtf(t[tx][ty + j * 8]);
}

// ---------------------------------------------------------------------------
// GEMM: 128m x 128n x 32k tile, 128 threads (4 warps 2x2, warp tile 64x64),
// 3-stage cp.async, 2 CTAs/SM. A smem [m][k32], Bt smem [n][k32], swizzled.
// SCATTER=1: round + scatter q/k into [bh][t][d], v into [bh][d][t].
// ---------------------------------------------------------------------------
#define BM 128
#define BN 128
#define BK 32
#define STG 3
#define ASZ (BM * BK)
#define BSZ (BN * BK)
#define GEMM_SMEM (STG * (ASZ + BSZ) * 4)   // 98304 B

template <int SCATTER>
__global__ void __launch_bounds__(128, 2) gemm_tc(
    const float* __restrict__ A, const float* __restrict__ Bt,
    float* __restrict__ C, int M, int N, int K)
{
    extern __shared__ float sh[];
    float* As = sh;
    float* Bs = sh + STG * ASZ;

    const int tid  = threadIdx.x;
    const int lane = tid & 31;
    const int w    = tid >> 5;        // 0..3
    const int wm   = w >> 1;          // 0..1 -> m*64
    const int wn   = w & 1;           // 0..1 -> n*64
    const int g    = lane >> 2;
    const int cq   = lane & 3;
    const int sub  = lane >> 3;       // 0..3 (ldmatrix sub-matrix)
    const int rl   = lane & 7;
    const int bm   = blockIdx.y << 7;
    const int bn   = blockIdx.x << 7;

    const int NIT = K >> 5;

    auto load_tile = [&](int kt, int s) {
        const float* Ag = A + (size_t)bm * K + kt * BK;
#pragma unroll
        for (int i = 0; i < 8; i++) {
            int idx = tid + i * 128;
            int r = idx >> 3, c = idx & 7;
            cp16(&As[s * ASZ + r * 32 + SWB(r, c) * 4], Ag + (size_t)r * K + c * 4);
        }
        const float* Bg = Bt + (size_t)bn * K + kt * BK;
#pragma unroll
        for (int i = 0; i < 8; i++) {
            int idx = tid + i * 128;
            int r = idx >> 3, c = idx & 7;
            cp16(&Bs[s * BSZ + r * 32 + SWB(r, c) * 4], Bg + (size_t)r * K + c * 4);
        }
    };

    float acc[4][8][4];
#pragma unroll
    for (int mi = 0; mi < 4; mi++)
#pragma unroll
        for (int ni = 0; ni < 8; ni++)
#pragma unroll
            for (int r = 0; r < 4; r++) acc[mi][ni][r] = 0.0f;

    load_tile(0, 0); CPCOMMIT();
    load_tile(1, 1); CPCOMMIT();

    int s_cur = 0, s_nxt = 2;
#pragma unroll 1
    for (int kt = 0; kt < NIT; kt++) {
        asm volatile("cp.async.wait_group 1;");
        __syncthreads();

        if (kt + 2 < NIT) load_tile(kt + 2, s_nxt);
        CPCOMMIT();

        const float* Asb = As + s_cur * ASZ;
        const float* Bsb = Bs + s_cur * BSZ;
        s_nxt = s_cur;
        s_cur = (s_cur == 2) ? 0 : s_cur + 1;

#pragma unroll
        for (int ks = 0; ks < 4; ks++) {
            const int chunk = ks * 2 + (sub >> 1);
            unsigned af[4][4], bf[4][4];
#pragma unroll
            for (int mi = 0; mi < 4; mi++) {
                const int row = wm * 64 + mi * 16 + (sub & 1) * 8 + rl;
                ldsm4(af[mi], Asb + row * 32 + SWB(row, chunk) * 4);
            }
#pragma unroll
            for (int p = 0; p < 4; p++) {
                const int row = wn * 64 + p * 16 + (sub & 1) * 8 + rl;
                ldsm4(bf[p], Bsb + row * 32 + SWB(row, chunk) * 4);
            }
#pragma unroll
            for (int mi = 0; mi < 4; mi++)
#pragma unroll
                for (int p = 0; p < 4; p++) {
                    mma_tf32(acc[mi][2 * p],     af[mi], bf[p][0], bf[p][2]);
                    mma_tf32(acc[mi][2 * p + 1], af[mi], bf[p][1], bf[p][3]);
                }
        }
    }

    // epilogue
#pragma unroll
    for (int mi = 0; mi < 4; mi++) {
        const int row = bm + wm * 64 + mi * 16 + g;
#pragma unroll
        for (int ni = 0; ni < 8; ni++) {
            const int col = bn + wn * 64 + ni * 8 + 2 * cq;
            if (SCATTER) {
                const int which = col >> 10;
                const int h     = (col & 1023) >> 6;
                const int d0    = col & 63;
                const int b     = row >> 11, t = row & 2047;
                if (which == 2) {
                    // V transposed: g_v[bh][d][t]
                    float* p = g_v + ((size_t)((b * 16 + h) * 64 + d0) << 11) + t;
                    p[0]            = rtf(acc[mi][ni][0]);
                    p[2048]         = rtf(acc[mi][ni][1]);
                    p[8]            = rtf(acc[mi][ni][2]);
                    p[2048 + 8]     = rtf(acc[mi][ni][3]);
                } else {
                    float* dst = (which == 0) ? g_q : g_k;
                    float* p = dst + ((size_t)((b * 16 + h) * 2048 + t) << 6) + d0;
                    *(float2*)p = make_float2(rtf(acc[mi][ni][0]), rtf(acc[mi][ni][1]));
                    *(float2*)(p + (8 << 6)) =
                        make_float2(rtf(acc[mi][ni][2]), rtf(acc[mi][ni][3]));
                }
            } else {
                *(float2*)&C[(size_t)row * N + col] =
                    make_float2(acc[mi][ni][0], acc[mi][ni][1]);
                *(float2*)&C[(size_t)(row + 8) * N + col] =
                    make_float2(acc[mi][ni][2], acc[mi][ni][3]);
            }
        }
    }
}

// ---------------------------------------------------------------------------
// Causal flash attention, 128 threads = 4 warps, 64 q rows/block, 2 CTAs/SM.
// Q fragments hoisted into registers (loop-invariant). K/V double-buffered.
// V is [d][t]. smem rows are 64 floats, swizzle SWA. 96 KB smem.
// ---------------------------------------------------------------------------
#define AQ  (64 * 64)
#define AKV (64 * 64)
#define ATTN_SMEM ((AQ + 4 * AKV + 64 * 64) * 4)   // 98304 B
#define SCL 0.180336880f   // 0.125 * log2(e)

__global__ void __launch_bounds__(128, 2) attn_tc()
{
    extern __shared__ float sh[];
    float* Qs = sh;                    // [64][64]
    float* Ks = sh + AQ;               // [2][64][64]  (rows = kpos)
    float* Vs = sh + AQ + 2 * AKV;     // [2][64][64]  (rows = d)
    float* Ps = sh + AQ + 4 * AKV;     // [64][64]

    const int tid  = threadIdx.x;
    const int lane = tid & 31;
    const int w    = tid >> 5;         // 0..3
    const int g    = lane >> 2;
    const int cq   = lane & 3;
    const int sub  = lane >> 3;
    const int rl   = lane & 7;
    const int bh   = blockIdx.y;
    const int q0   = blockIdx.x << 6;

    const float* Qg  = g_q + ((size_t)bh * NT + q0) * ND;
    const float* Kg0 = g_k + (size_t)bh * NT * ND;
    const float* Vg0 = g_v + (size_t)bh * ND * NT;   // [d][t]

    auto load_kv = [&](int kt, int s) {
        const float* Kg = Kg0 + ((size_t)kt << 12);
        const float* Vg = Vg0 + (kt << 6);
#pragma unroll
        for (int i = 0; i < 8; i++) {
            int idx = tid + i * 128;
            int r = idx >> 4, c = idx & 15;
            cp16(&Ks[s * AKV + r * 64 + SWA(r, c) * 4], Kg + r * 64 + c * 4);
            cp16(&Vs[s * AKV + r * 64 + SWA(r, c) * 4], Vg + (size_t)r * NT + c * 4);
        }
    };

    // Q + KV(0) in group 0
#pragma unroll
    for (int i = 0; i < 8; i++) {
        int idx = tid + i * 128;
        int r = idx >> 4, c = idx & 15;
        cp16(&Qs[r * 64 + SWA(r, c) * 4], Qg + r * 64 + c * 4);
    }
    load_kv(0, 0);
    CPCOMMIT();
    asm volatile("cp.async.wait_group 0;");
    __syncthreads();

    const int rq    = w * 16 + g;
    const int rowA  = w * 16 + (sub & 1) * 8 + rl;   // ldmatrix A row
    const int ktmax = q0 >> 6;

    // hoist Q fragments (loop-invariant)
    unsigned qf[8][4];
#pragma unroll
    for (int ks = 0; ks < 8; ks++) {
        const int chunk = ks * 2 + (sub >> 1);
        ldsm4(qf[ks], Qs + rowA * 64 + SWA(rowA, chunk) * 4);
    }

    float m0 = -1e30f, m1 = -1e30f, l0 = 0.0f, l1 = 0.0f;
    float o[8][4];
#pragma unroll
    for (int nt = 0; nt < 8; nt++)
#pragma unroll
        for (int r = 0; r < 4; r++) o[nt][r] = 0.0f;

    for (int kt = 0; kt <= ktmax; kt++) {
        // prefetch next K/V while computing this tile
        if (kt < ktmax) { load_kv(kt + 1, (kt + 1) & 1); CPCOMMIT(); }

        const float* Kb = Ks + (kt & 1) * AKV;
        const float* Vb = Vs + (kt & 1) * AKV;

        float s[8][4];
#pragma unroll
        for (int nt = 0; nt < 8; nt++)
#pragma unroll
            for (int r = 0; r < 4; r++) s[nt][r] = 0.0f;

        // S = Q K^T
#pragma unroll
        for (int ks = 0; ks < 8; ks++) {
            const int chunk = ks * 2 + (sub >> 1);
#pragma unroll
            for (int p = 0; p < 4; p++) {
                const int rk = p * 16 + (sub & 1) * 8 + rl;
                unsigned bk[4];
                ldsm4(bk, Kb + rk * 64 + SWA(rk, chunk) * 4);
                mma_tf32(s[2 * p],     qf[ks], bk[0], bk[2]);
                mma_tf32(s[2 * p + 1], qf[ks], bk[1], bk[3]);
            }
        }

#pragma unroll
        for (int nt = 0; nt < 8; nt++)
#pragma unroll
            for (int r = 0; r < 4; r++) s[nt][r] *= SCL;

        if (kt == ktmax) {   // diagonal tile: mask
            const int r0 = rq, r1 = rq + 8;
#pragma unroll
            for (int nt = 0; nt < 8; nt++) {
                int gc = nt * 8 + 2 * cq;
                if (gc     > r0) s[nt][0] = -1e30f;
                if (gc + 1 > r0) s[nt][1] = -1e30f;
                if (gc     > r1) s[nt][2] = -1e30f;
                if (gc + 1 > r1) s[nt][3] = -1e30f;
            }
        }

        // online softmax (log2 domain)
        float rm0 = -1e30f, rm1 = -1e30f;
#pragma unroll
        for (int nt = 0; nt < 8; nt++) {
            rm0 = fmaxf(rm0, fmaxf(s[nt][0], s[nt][1]));
            rm1 = fmaxf(rm1, fmaxf(s[nt][2], s[nt][3]));
        }
        rm0 = fmaxf(rm0, __shfl_xor_sync(0xffffffffu, rm0, 1));
        rm0 = fmaxf(rm0, __shfl_xor_sync(0xffffffffu, rm0, 2));
        rm1 = fmaxf(rm1, __shfl_xor_sync(0xffffffffu, rm1, 1));
        rm1 = fmaxf(rm1, __shfl_xor_sync(0xffffffffu, rm1, 2));

        float mn0 = fmaxf(m0, rm0), mn1 = fmaxf(m1, rm1);
        float sc0 = fexp2(m0 - mn0), sc1 = fexp2(m1 - mn1);
        float rs0 = 0.0f, rs1 = 0.0f;
#pragma unroll
        for (int nt = 0; nt < 8; nt++) {
            s[nt][0] = fexp2(s[nt][0] - mn0);
            s[nt][1] = fexp2(s[nt][1] - mn0);
            s[nt][2] = fexp2(s[nt][2] - mn1);
            s[nt][3] = fexp2(s[nt][3] - mn1);
            rs0 += s[nt][0] + s[nt][1];
            rs1 += s[nt][2] + s[nt][3];
        }
        rs0 += __shfl_xor_sync(0xffffffffu, rs0, 1);
        rs0 += __shfl_xor_sync(0xffffffffu, rs0, 2);
        rs1 += __shfl_xor_sync(0xffffffffu, rs1, 1);
        rs1 += __shfl_xor_sync(0xffffffffu, rs1, 2);
        l0 = l0 * sc0 + rs0;
        l1 = l1 * sc1 + rs1;
        m0 = mn0; m1 = mn1;
#pragma unroll
        for (int nt = 0; nt < 8; nt++) {
            o[nt][0] *= sc0; o[nt][1] *= sc0;
            o[nt][2] *= sc1; o[nt][3] *= sc1;
        }

        // P -> smem (warp-private rows), swizzled, rounded
#pragma unroll
        for (int nt = 0; nt < 8; nt++) {
            const int ch = nt * 2 + (cq >> 1);
            const int of = (2 * cq) & 3;
            *(float2*)&Ps[rq * 64 + SWA(rq, ch) * 4 + of] =
                make_float2(rtf(s[nt][0]), rtf(s[nt][1]));
            *(float2*)&Ps[(rq + 8) * 64 + SWA(rq + 8, ch) * 4 + of] =
                make_float2(rtf(s[nt][2]), rtf(s[nt][3]));
        }
        __syncwarp();

        // O += P V   (V is [d][t] in smem: rows = d)
#pragma unroll
        for (int ks = 0; ks < 8; ks++) {
            const int chunk = ks * 2 + (sub >> 1);
            unsigned ap[4];
            ldsm4(ap, Ps + rowA * 64 + SWA(rowA, chunk) * 4);
#pragma unroll
            for (int p = 0; p < 4; p++) {
                const int rv = p * 16 + (sub & 1) * 8 + rl;   // d row
                unsigned bv[4];
                ldsm4(bv, Vb + rv * 64 + SWA(rv, chunk) * 4);
                mma_tf32(o[2 * p],     ap, bv[0], bv[2]);
                mma_tf32(o[2 * p + 1], ap, bv[1], bv[3]);
            }
        }

        // wait next K/V arrival; sync so buffer (kt+2)&1 is safe to overwrite
        if (kt < ktmax) asm volatile("cp.async.wait_group 0;");
        __syncthreads();
    }

    const int b = bh >> 4;
    const int h = bh & 15;
    const float inv0 = 1.0f / l0;
    const float inv1 = 1.0f / l1;
    float* Og = g_att + ((size_t)(b * NT + q0 + rq)) * NC + (h << 6);
#pragma unroll
    for (int nt = 0; nt < 8; nt++) {
        int col = nt * 8 + 2 * cq;
        *(float2*)(Og + col) =
            make_float2(rtf(o[nt][0] * inv0), rtf(o[nt][1] * inv0));
        *(float2*)(Og + (size_t)8 * NC + col) =
            make_float2(rtf(o[nt][2] * inv1), rtf(o[nt][3] * inv1));
    }
}

// ---------------------------------------------------------------------------
// launch
// ---------------------------------------------------------------------------
extern "C" void kernel_launch(void* const* d_in, const int* in_sizes, int n_in,
                              void* d_out, int out_size)
{
    const float* x     = (const float*)d_in[0];
    const float* Wqkv  = (const float*)d_in[1];
    const float* Wproj = (const float*)d_in[2];
    float* out = (float*)d_out;

    void *px, *pwqkv, *pwproj, *patt;
    cudaGetSymbolAddress(&px, g_x);
    cudaGetSymbolAddress(&pwqkv, g_wqkv);
    cudaGetSymbolAddress(&pwproj, g_wproj);
    cudaGetSymbolAddress(&patt, g_att);

    cudaFuncSetAttribute(gemm_tc<1>,
                         cudaFuncAttributeMaxDynamicSharedMemorySize, GEMM_SMEM);
    cudaFuncSetAttribute(gemm_tc<0>,
                         cudaFuncAttributeMaxDynamicSharedMemorySize, GEMM_SMEM);
    cudaFuncSetAttribute(attn_tc,
                         cudaFuncAttributeMaxDynamicSharedMemorySize, ATTN_SMEM);

    // 0) pre-round x; round+transpose weights to [n][k]
    cvt_kernel<<<(NM * NC / 4 + 255) / 256, 256>>>(
        (const float4*)x, (uint4*)px, NM * NC / 4);
    cvt_t_kernel<<<dim3(3 * NC / 32, NC / 32), 256>>>(
        Wqkv, (float*)pwqkv, NC, 3 * NC);
    cvt_t_kernel<<<dim3(NC / 32, NC / 32), 256>>>(
        Wproj, (float*)pwproj, NC, NC);

    // 1) qkv = x @ Wqkv -> scatter q,k [bh][t][d], v [bh][d][t]
    gemm_tc<1><<<dim3(3 * NC / BN, NM / BM), 128, GEMM_SMEM>>>(
        (const float*)px, (const float*)pwqkv, nullptr, NM, 3 * NC, NC);

    // 2) causal attention -> g_att (rounded)
    attn_tc<<<dim3(NT / 64, NBH), 128, ATTN_SMEM>>>();

    // 3) out = g_att @ Wproj
    gemm_tc<0><<<dim3(NC / BN, NM / BM), 128, GEMM_SMEM>>>(
        (const float*)patt, (const float*)pwproj, out, NM, NC, NC);
}

// round 10
// speedup vs baseline: 3.8420x; 1.0036x over previous
#include <cuda_runtime.h>

// ---------------------------------------------------------------------------
// B=4, T=2048, C=1024, H=16, D=64.  All matmuls: mma.sync.m16n8k8.tf32.
// ldmatrix fragments, cp.async pipelines, pre-rounded tf32 inputs.
// GEMM: 128x128x32 tile, 4 warps (64x64 warp tile), 3 stages, 2 CTAs/SM,
//       prefetch issued after first MMA chunk.
// Attention: 64-q blocks, 2 CTAs/SM, Q frags in regs, diagonal specialized,
//       reversed launch order.
// ---------------------------------------------------------------------------

#define NBH 64
#define NT  2048
#define ND  64
#define NC  1024
#define NM  8192

__device__ float g_q[NBH * NT * ND];
__device__ float g_k[NBH * NT * ND];
__device__ float g_v[NBH * NT * ND];        // transposed: [bh][d][t]
__device__ float g_att[NM * NC];
__device__ float g_x[NM * NC];
__device__ float g_wqkv[3 * NC * NC];       // transposed: [n][k]
__device__ float g_wproj[NC * NC];          // transposed: [n][k]

__device__ __forceinline__ unsigned f2tf(float f) {
    unsigned u;
    asm("cvt.rna.tf32.f32 %0, %1;" : "=r"(u) : "f"(f));
    return u;
}
__device__ __forceinline__ float rtf(float x) { return __uint_as_float(f2tf(x)); }

__device__ __forceinline__ void mma_tf32(float* c, const unsigned* a,
                                         unsigned b0, unsigned b1) {
    asm volatile(
        "mma.sync.aligned.m16n8k8.row.col.f32.tf32.tf32.f32 "
        "{%0,%1,%2,%3}, {%4,%5,%6,%7}, {%8,%9}, {%0,%1,%2,%3};"
        : "+f"(c[0]), "+f"(c[1]), "+f"(c[2]), "+f"(c[3])
        : "r"(a[0]), "r"(a[1]), "r"(a[2]), "r"(a[3]), "r"(b0), "r"(b1));
}

__device__ __forceinline__ void ldsm4(unsigned* r, const float* p) {
    unsigned a = (unsigned)__cvta_generic_to_shared(p);
    asm volatile("ldmatrix.sync.aligned.m8n8.x4.shared.b16 {%0,%1,%2,%3}, [%4];"
                 : "=r"(r[0]), "=r"(r[1]), "=r"(r[2]), "=r"(r[3]) : "r"(a));
}

__device__ __forceinline__ void cp16(void* smem_dst, const void* gmem_src) {
    unsigned sa = (unsigned)__cvta_generic_to_shared(smem_dst);
    asm volatile("cp.async.cg.shared.global [%0], [%1], 16;" :: "r"(sa), "l"(gmem_src));
}
#define CPCOMMIT() asm volatile("cp.async.commit_group;")

__device__ __forceinline__ float fexp2(float x) {
    float y;
    asm("ex2.approx.f32 %0, %1;" : "=f"(y) : "f"(x));
    return y;
}

// swizzles (chunk = 4-float group within a row)
#define SWB(r, c) ((c) ^ ((r) & 7))          // rows of 32 floats (GEMM BK=32)
#define SWA(r, c) ((c) ^ ((r) & 7))          // rows of 64 floats (attention)

// ---------------------------------------------------------------------------
// pre-round kernels
// ---------------------------------------------------------------------------
__global__ void cvt_kernel(const float4* __restrict__ src,
                           uint4* __restrict__ dst, int n4)
{
    int i = blockIdx.x * 256 + threadIdx.x;
    if (i < n4) {
        float4 v = src[i];
        uint4 u;
        u.x = f2tf(v.x); u.y = f2tf(v.y); u.z = f2tf(v.z); u.w = f2tf(v.w);
        dst[i] = u;
    }
}

// round + transpose W[K][N] -> Wt[N][K]
__global__ void cvt_t_kernel(const float* __restrict__ src,
                             float* __restrict__ dst, int K, int N)
{
    __shared__ float t[32][33];
    const int n0 = blockIdx.x << 5;
    const int k0 = blockIdx.y << 5;
    const int tx = threadIdx.x & 31;
    const int ty = threadIdx.x >> 5;   // 0..7
#pragma unroll
    for (int j = 0; j < 4; j++)
        t[ty + j * 8][tx] = src[(size_t)(k0 + ty + j * 8) * N + n0 + tx];
    __syncthreads();
#pragma unroll
    for (int j = 0; j < 4; j++)
        dst[(size_t)(n0 + ty + j * 8) * K + k0 + tx] = rtf(t[tx][ty + j * 8]);
}

// ---------------------------------------------------------------------------
// GEMM: 128m x 128n x 32k tile, 128 threads (4 warps 2x2, warp tile 64x64),
// 3-stage cp.async, 2 CTAs/SM. A smem [m][k32], Bt smem [n][k32], swizzled.
// SCATTER=1: round + scatter q/k into [bh][t][d], v into [bh][d][t].
// ---------------------------------------------------------------------------
#define BM 128
#define BN 128
#define BK 32
#define STG 3
#define ASZ (BM * BK)
#define BSZ (BN * BK)
#define GEMM_SMEM (STG * (ASZ + BSZ) * 4)   // 98304 B

template <int SCATTER>
__global__ void __launch_bounds__(128, 2) gemm_tc(
    const float* __restrict__ A, const float* __restrict__ Bt,
    float* __restrict__ C, int M, int N, int K)
{
    extern __shared__ float sh[];
    float* As = sh;
    float* Bs = sh + STG * ASZ;

    const int tid  = threadIdx.x;
    const int lane = tid & 31;
    const int w    = tid >> 5;        // 0..3
    const int wm   = w >> 1;          // 0..1 -> m*64
    const int wn   = w & 1;           // 0..1 -> n*64
    const int g    = lane >> 2;
    const int cq   = lane & 3;
    const int sub  = lane >> 3;       // 0..3 (ldmatrix sub-matrix)
    const int rl   = lane & 7;
    const int bm   = blockIdx.y << 7;
    const int bn   = blockIdx.x << 7;

    const int NIT = K >> 5;

    auto load_tile = [&](int kt, int s) {
        const float* Ag = A + (size_t)bm * K + kt * BK;
#pragma unroll
        for (int i = 0; i < 8; i++) {
            int idx = tid + i * 128;
            int r = idx >> 3, c = idx & 7;
            cp16(&As[s * ASZ + r * 32 + SWB(r, c) * 4], Ag + (size_t)r * K + c * 4);
        }
        const float* Bg = Bt + (size_t)bn * K + kt * BK;
#pragma unroll
        for (int i = 0; i < 8; i++) {
            int idx = tid + i * 128;
            int r = idx >> 3, c = idx & 7;
            cp16(&Bs[s * BSZ + r * 32 + SWB(r, c) * 4], Bg + (size_t)r * K + c * 4);
        }
    };

    float acc[4][8][4];
#pragma unroll
    for (int mi = 0; mi < 4; mi++)
#pragma unroll
        for (int ni = 0; ni < 8; ni++)
#pragma unroll
            for (int r = 0; r < 4; r++) acc[mi][ni][r] = 0.0f;

    load_tile(0, 0); CPCOMMIT();
    load_tile(1, 1); CPCOMMIT();

    int s_cur = 0, s_nxt = 2;
#pragma unroll 1
    for (int kt = 0; kt < NIT; kt++) {
        asm volatile("cp.async.wait_group 1;");
        __syncthreads();

        const float* Asb = As + s_cur * ASZ;
        const float* Bsb = Bs + s_cur * BSZ;
        const int s_pf = s_nxt;
        s_nxt = s_cur;
        s_cur = (s_cur == 2) ? 0 : s_cur + 1;

        auto do_chunk = [&](int ks) {
            const int chunk = ks * 2 + (sub >> 1);
            unsigned af[4][4], bf[4][4];
#pragma unroll
            for (int mi = 0; mi < 4; mi++) {
                const int row = wm * 64 + mi * 16 + (sub & 1) * 8 + rl;
                ldsm4(af[mi], Asb + row * 32 + SWB(row, chunk) * 4);
            }
#pragma unroll
            for (int p = 0; p < 4; p++) {
                const int row = wn * 64 + p * 16 + (sub & 1) * 8 + rl;
                ldsm4(bf[p], Bsb + row * 32 + SWB(row, chunk) * 4);
            }
#pragma unroll
            for (int mi = 0; mi < 4; mi++)
#pragma unroll
                for (int p = 0; p < 4; p++) {
                    mma_tf32(acc[mi][2 * p],     af[mi], bf[p][0], bf[p][2]);
                    mma_tf32(acc[mi][2 * p + 1], af[mi], bf[p][1], bf[p][3]);
                }
        };

        // chunk 0 first, then issue next tile's loads (overlap with compute)
        do_chunk(0);
        if (kt + 2 < NIT) load_tile(kt + 2, s_pf);
        CPCOMMIT();
#pragma unroll
        for (int ks = 1; ks < 4; ks++) do_chunk(ks);
    }

    // epilogue
#pragma unroll
    for (int mi = 0; mi < 4; mi++) {
        const int row = bm + wm * 64 + mi * 16 + g;
#pragma unroll
        for (int ni = 0; ni < 8; ni++) {
            const int col = bn + wn * 64 + ni * 8 + 2 * cq;
            if (SCATTER) {
                const int which = col >> 10;
                const int h     = (col & 1023) >> 6;
                const int d0    = col & 63;
                const int b     = row >> 11, t = row & 2047;
                if (which == 2) {
                    // V transposed: g_v[bh][d][t]
                    float* p = g_v + ((size_t)((b * 16 + h) * 64 + d0) << 11) + t;
                    p[0]            = rtf(acc[mi][ni][0]);
                    p[2048]         = rtf(acc[mi][ni][1]);
                    p[8]            = rtf(acc[mi][ni][2]);
                    p[2048 + 8]     = rtf(acc[mi][ni][3]);
                } else {
                    float* dst = (which == 0) ? g_q : g_k;
                    float* p = dst + ((size_t)((b * 16 + h) * 2048 + t) << 6) + d0;
                    *(float2*)p = make_float2(rtf(acc[mi][ni][0]), rtf(acc[mi][ni][1]));
                    *(float2*)(p + (8 << 6)) =
                        make_float2(rtf(acc[mi][ni][2]), rtf(acc[mi][ni][3]));
                }
            } else {
                *(float2*)&C[(size_t)row * N + col] =
                    make_float2(acc[mi][ni][0], acc[mi][ni][1]);
                *(float2*)&C[(size_t)(row + 8) * N + col] =
                    make_float2(acc[mi][ni][2], acc[mi][ni][3]);
            }
        }
    }
}

// ---------------------------------------------------------------------------
// Causal flash attention, 128 threads = 4 warps, 64 q rows/block, 2 CTAs/SM.
// Q fragments hoisted. K/V double-buffered. V is [d][t]. Diagonal tile
// specialized per-warp (warp w only needs kpos tiles < 2w+2).
// ---------------------------------------------------------------------------
#define AQ  (64 * 64)
#define AKV (64 * 64)
#define ATTN_SMEM ((AQ + 4 * AKV + 64 * 64) * 4)   // 98304 B
#define SCL 0.180336880f   // 0.125 * log2(e)

__global__ void __launch_bounds__(128, 2) attn_tc()
{
    extern __shared__ float sh[];
    float* Qs = sh;                    // [64][64]
    float* Ks = sh + AQ;               // [2][64][64]  (rows = kpos)
    float* Vs = sh + AQ + 2 * AKV;     // [2][64][64]  (rows = d)
    float* Ps = sh + AQ + 4 * AKV;     // [64][64]

    const int tid  = threadIdx.x;
    const int lane = tid & 31;
    const int w    = tid >> 5;         // 0..3
    const int g    = lane >> 2;
    const int cq   = lane & 3;
    const int sub  = lane >> 3;
    const int rl   = lane & 7;
    const int bh   = blockIdx.y;
    const int q0   = (gridDim.x - 1 - blockIdx.x) << 6;   // big tiles first

    const float* Qg  = g_q + ((size_t)bh * NT + q0) * ND;
    const float* Kg0 = g_k + (size_t)bh * NT * ND;
    const float* Vg0 = g_v + (size_t)bh * ND * NT;   // [d][t]

    auto load_kv = [&](int kt, int s) {
        const float* Kg = Kg0 + ((size_t)kt << 12);
        const float* Vg = Vg0 + (kt << 6);
#pragma unroll
        for (int i = 0; i < 8; i++) {
            int idx = tid + i * 128;
            int r = idx >> 4, c = idx & 15;
            cp16(&Ks[s * AKV + r * 64 + SWA(r, c) * 4], Kg + r * 64 + c * 4);
            cp16(&Vs[s * AKV + r * 64 + SWA(r, c) * 4], Vg + (size_t)r * NT + c * 4);
        }
    };

    // Q + KV(0) in group 0
#pragma unroll
    for (int i = 0; i < 8; i++) {
        int idx = tid + i * 128;
        int r = idx >> 4, c = idx & 15;
        cp16(&Qs[r * 64 + SWA(r, c) * 4], Qg + r * 64 + c * 4);
    }
    load_kv(0, 0);
    CPCOMMIT();
    asm volatile("cp.async.wait_group 0;");
    __syncthreads();

    const int rq    = w * 16 + g;
    const int rowA  = w * 16 + (sub & 1) * 8 + rl;   // ldmatrix A row
    const int ktmax = q0 >> 6;
    const int NTD   = 2 * w + 2;   // diag: kpos 8-tiles needed by this warp

    // hoist Q fragments (loop-invariant)
    unsigned qf[8][4];
#pragma unroll
    for (int ks = 0; ks < 8; ks++) {
        const int chunk = ks * 2 + (sub >> 1);
        ldsm4(qf[ks], Qs + rowA * 64 + SWA(rowA, chunk) * 4);
    }

    float m0 = -1e30f, m1 = -1e30f, l0 = 0.0f, l1 = 0.0f;
    float o[8][4];
#pragma unroll
    for (int nt = 0; nt < 8; nt++)
#pragma unroll
        for (int r = 0; r < 4; r++) o[nt][r] = 0.0f;

    // ---------------- main loop: non-diagonal tiles (no masking) ----------
    for (int kt = 0; kt < ktmax; kt++) {
        const float* Kb = Ks + (kt & 1) * AKV;
        const float* Vb = Vs + (kt & 1) * AKV;

        float s[8][4];
#pragma unroll
        for (int nt = 0; nt < 8; nt++)
#pragma unroll
            for (int r = 0; r < 4; r++) s[nt][r] = 0.0f;

        // S chunk ks=0, then issue next K/V prefetch, then chunks 1..7
        {
            const int chunk = (sub >> 1);
#pragma unroll
            for (int p = 0; p < 4; p++) {
                const int rk = p * 16 + (sub & 1) * 8 + rl;
                unsigned bk[4];
                ldsm4(bk, Kb + rk * 64 + SWA(rk, chunk) * 4);
                mma_tf32(s[2 * p],     qf[0], bk[0], bk[2]);
                mma_tf32(s[2 * p + 1], qf[0], bk[1], bk[3]);
            }
        }
        load_kv(kt + 1, (kt + 1) & 1);
        CPCOMMIT();
#pragma unroll
        for (int ks = 1; ks < 8; ks++) {
            const int chunk = ks * 2 + (sub >> 1);
#pragma unroll
            for (int p = 0; p < 4; p++) {
                const int rk = p * 16 + (sub & 1) * 8 + rl;
                unsigned bk[4];
                ldsm4(bk, Kb + rk * 64 + SWA(rk, chunk) * 4);
                mma_tf32(s[2 * p],     qf[ks], bk[0], bk[2]);
                mma_tf32(s[2 * p + 1], qf[ks], bk[1], bk[3]);
            }
        }

#pragma unroll
        for (int nt = 0; nt < 8; nt++)
#pragma unroll
            for (int r = 0; r < 4; r++) s[nt][r] *= SCL;

        // online softmax (log2 domain)
        float rm0 = -1e30f, rm1 = -1e30f;
#pragma unroll
        for (int nt = 0; nt < 8; nt++) {
            rm0 = fmaxf(rm0, fmaxf(s[nt][0], s[nt][1]));
            rm1 = fmaxf(rm1, fmaxf(s[nt][2], s[nt][3]));
        }
        rm0 = fmaxf(rm0, __shfl_xor_sync(0xffffffffu, rm0, 1));
        rm0 = fmaxf(rm0, __shfl_xor_sync(0xffffffffu, rm0, 2));
        rm1 = fmaxf(rm1, __shfl_xor_sync(0xffffffffu, rm1, 1));
        rm1 = fmaxf(rm1, __shfl_xor_sync(0xffffffffu, rm1, 2));

        float mn0 = fmaxf(m0, rm0), mn1 = fmaxf(m1, rm1);
        float sc0 = fexp2(m0 - mn0), sc1 = fexp2(m1 - mn1);
        float rs0 = 0.0f, rs1 = 0.0f;
#pragma unroll
        for (int nt = 0; nt < 8; nt++) {
            s[nt][0] = fexp2(s[nt][0] - mn0);
            s[nt][1] = fexp2(s[nt][1] - mn0);
            s[nt][2] = fexp2(s[nt][2] - mn1);
            s[nt][3] = fexp2(s[nt][3] - mn1);
            rs0 += s[nt][0] + s[nt][1];
            rs1 += s[nt][2] + s[nt][3];
        }
        rs0 += __shfl_xor_sync(0xffffffffu, rs0, 1);
        rs0 += __shfl_xor_sync(0xffffffffu, rs0, 2);
        rs1 += __shfl_xor_sync(0xffffffffu, rs1, 1);
        rs1 += __shfl_xor_sync(0xffffffffu, rs1, 2);
        l0 = l0 * sc0 + rs0;
        l1 = l1 * sc1 + rs1;
        m0 = mn0; m1 = mn1;
#pragma unroll
        for (int nt = 0; nt < 8; nt++) {
            o[nt][0] *= sc0; o[nt][1] *= sc0;
            o[nt][2] *= sc1; o[nt][3] *= sc1;
        }

        // P -> smem (warp-private rows), swizzled, rounded
#pragma unroll
        for (int nt = 0; nt < 8; nt++) {
            const int ch = nt * 2 + (cq >> 1);
            const int of = (2 * cq) & 3;
            *(float2*)&Ps[rq * 64 + SWA(rq, ch) * 4 + of] =
                make_float2(rtf(s[nt][0]), rtf(s[nt][1]));
            *(float2*)&Ps[(rq + 8) * 64 + SWA(rq + 8, ch) * 4 + of] =
                make_float2(rtf(s[nt][2]), rtf(s[nt][3]));
        }
        __syncwarp();

        // O += P V   (V is [d][t] in smem: rows = d)
#pragma unroll
        for (int ks = 0; ks < 8; ks++) {
            const int chunk = ks * 2 + (sub >> 1);
            unsigned ap[4];
            ldsm4(ap, Ps + rowA * 64 + SWA(rowA, chunk) * 4);
#pragma unroll
            for (int p = 0; p < 4; p++) {
                const int rv = p * 16 + (sub & 1) * 8 + rl;   // d row
                unsigned bv[4];
                ldsm4(bv, Vb + rv * 64 + SWA(rv, chunk) * 4);
                mma_tf32(o[2 * p],     ap, bv[0], bv[2]);
                mma_tf32(o[2 * p + 1], ap, bv[1], bv[3]);
            }
        }

        asm volatile("cp.async.wait_group 0;");
        __syncthreads();
    }

    // ---------------- diagonal tile (kt == ktmax), per-warp reduced range --
    {
        const float* Kb = Ks + (ktmax & 1) * AKV;
        const float* Vb = Vs + (ktmax & 1) * AKV;

        float s[8][4];
#pragma unroll
        for (int nt = 0; nt < 8; nt++)
#pragma unroll
            for (int r = 0; r < 4; r++) s[nt][r] = 0.0f;

        // S: only kpos tile-pairs p <= w needed (warp-uniform guard)
#pragma unroll
        for (int ks = 0; ks < 8; ks++) {
            const int chunk = ks * 2 + (sub >> 1);
#pragma unroll
            for (int p = 0; p < 4; p++) {
                if (p <= w) {
                    const int rk = p * 16 + (sub & 1) * 8 + rl;
                    unsigned bk[4];
                    ldsm4(bk, Kb + rk * 64 + SWA(rk, chunk) * 4);
                    mma_tf32(s[2 * p],     qf[ks], bk[0], bk[2]);
                    mma_tf32(s[2 * p + 1], qf[ks], bk[1], bk[3]);
                }
            }
        }

        // scale + causal mask (nt < NTD only)
        const int r0 = rq, r1 = rq + 8;
#pragma unroll
        for (int nt = 0; nt < 8; nt++) {
            if (nt < NTD) {
                int gc = nt * 8 + 2 * cq;
                s[nt][0] = (gc     <= r0) ? s[nt][0] * SCL : -1e30f;
                s[nt][1] = (gc + 1 <= r0) ? s[nt][1] * SCL : -1e30f;
                s[nt][2] = (gc     <= r1) ? s[nt][2] * SCL : -1e30f;
                s[nt][3] = (gc + 1 <= r1) ? s[nt][3] * SCL : -1e30f;
            }
        }

        float rm0 = -1e30f, rm1 = -1e30f;
#pragma unroll
        for (int nt = 0; nt < 8; nt++) {
            if (nt < NTD) {
                rm0 = fmaxf(rm0, fmaxf(s[nt][0], s[nt][1]));
                rm1 = fmaxf(rm1, fmaxf(s[nt][2], s[nt][3]));
            }
        }
        rm0 = fmaxf(rm0, __shfl_xor_sync(0xffffffffu, rm0, 1));
        rm0 = fmaxf(rm0, __shfl_xor_sync(0xffffffffu, rm0, 2));
        rm1 = fmaxf(rm1, __shfl_xor_sync(0xffffffffu, rm1, 1));
        rm1 = fmaxf(rm1, __shfl_xor_sync(0xffffffffu, rm1, 2));

        float mn0 = fmaxf(m0, rm0), mn1 = fmaxf(m1, rm1);
        float sc0 = fexp2(m0 - mn0), sc1 = fexp2(m1 - mn1);
        float rs0 = 0.0f, rs1 = 0.0f;
#pragma unroll
        for (int nt = 0; nt < 8; nt++) {
            if (nt < NTD) {
                s[nt][0] = fexp2(s[nt][0] - mn0);
                s[nt][1] = fexp2(s[nt][1] - mn0);
                s[nt][2] = fexp2(s[nt][2] - mn1);
                s[nt][3] = fexp2(s[nt][3] - mn1);
                rs0 += s[nt][0] + s[nt][1];
                rs1 += s[nt][2] + s[nt][3];
            }
        }
        rs0 += __shfl_xor_sync(0xffffffffu, rs0, 1);
        rs0 += __shfl_xor_sync(0xffffffffu, rs0, 2);
        rs1 += __shfl_xor_sync(0xffffffffu, rs1, 1);
        rs1 += __shfl_xor_sync(0xffffffffu, rs1, 2);
        l0 = l0 * sc0 + rs0;
        l1 = l1 * sc1 + rs1;
#pragma unroll
        for (int nt = 0; nt < 8; nt++) {
            o[nt][0] *= sc0; o[nt][1] *= sc0;
            o[nt][2] *= sc1; o[nt][3] *= sc1;
        }

#pragma unroll
        for (int nt = 0; nt < 8; nt++) {
            if (nt < NTD) {
                const int ch = nt * 2 + (cq >> 1);
                const int of = (2 * cq) & 3;
                *(float2*)&Ps[rq * 64 + SWA(rq, ch) * 4 + of] =
                    make_float2(rtf(s[nt][0]), rtf(s[nt][1]));
                *(float2*)&Ps[(rq + 8) * 64 + SWA(rq + 8, ch) * 4 + of] =
                    make_float2(rtf(s[nt][2]), rtf(s[nt][3]));
            }
        }
        __syncwarp();

        // PV: only kpos chunks ks < NTD contribute (P beyond is masked-zero)
#pragma unroll
        for (int ks = 0; ks < 8; ks++) {
            if (ks < NTD) {
                const int chunk = ks * 2 + (sub >> 1);
                unsigned ap[4];
                ldsm4(ap, Ps + rowA * 64 + SWA(rowA, chunk) * 4);
#pragma unroll
                for (int p = 0; p < 4; p++) {
                    const int rv = p * 16 + (sub & 1) * 8 + rl;
                    unsigned bv[4];
                    ldsm4(bv, Vb + rv * 64 + SWA(rv, chunk) * 4);
                    mma_tf32(o[2 * p],     ap, bv[0], bv[2]);
                    mma_tf32(o[2 * p + 1], ap, bv[1], bv[3]);
                }
            }
        }
    }

    const int b = bh >> 4;
    const int h = bh & 15;
    const float inv0 = 1.0f / l0;
    const float inv1 = 1.0f / l1;
    float* Og = g_att + ((size_t)(b * NT + q0 + rq)) * NC + (h << 6);
#pragma unroll
    for (int nt = 0; nt < 8; nt++) {
        int col = nt * 8 + 2 * cq;
        *(float2*)(Og + col) =
            make_float2(rtf(o[nt][0] * inv0), rtf(o[nt][1] * inv0));
        *(float2*)(Og + (size_t)8 * NC + col) =
            make_float2(rtf(o[nt][2] * inv1), rtf(o[nt][3] * inv1));
    }
}

// ---------------------------------------------------------------------------
// launch
// ---------------------------------------------------------------------------
extern "C" void kernel_launch(void* const* d_in, const int* in_sizes, int n_in,
                              void* d_out, int out_size)
{
    const float* x     = (const float*)d_in[0];
    const float* Wqkv  = (const float*)d_in[1];
    const float* Wproj = (const float*)d_in[2];
    float* out = (float*)d_out;

    void *px, *pwqkv, *pwproj, *patt;
    cudaGetSymbolAddress(&px, g_x);
    cudaGetSymbolAddress(&pwqkv, g_wqkv);
    cudaGetSymbolAddress(&pwproj, g_wproj);
    cudaGetSymbolAddress(&patt, g_att);

    cudaFuncSetAttribute(gemm_tc<1>,
                         cudaFuncAttributeMaxDynamicSharedMemorySize, GEMM_SMEM);
    cudaFuncSetAttribute(gemm_tc<0>,
                         cudaFuncAttributeMaxDynamicSharedMemorySize, GEMM_SMEM);
    cudaFuncSetAttribute(attn_tc,
                         cudaFuncAttributeMaxDynamicSharedMemorySize, ATTN_SMEM);

    // 0) pre-round x; round+transpose weights to [n][k]
    cvt_kernel<<<(NM * NC / 4 + 255) / 256, 256>>>(
        (const float4*)x, (uint4*)px, NM * NC / 4);
    cvt_t_kernel<<<dim3(3 * NC / 32, NC / 32), 256>>>(
        Wqkv, (float*)pwqkv, NC, 3 * NC);
    cvt_t_kernel<<<dim3(NC / 32, NC / 32), 256>>>(
        Wproj, (float*)pwproj, NC, NC);

    // 1) qkv = x @ Wqkv -> scatter q,k [bh][t][d], v [bh][d][t]
    gemm_tc<1><<<dim3(3 * NC / BN, NM / BM), 128, GEMM_SMEM>>>(
        (const float*)px, (const float*)pwqkv, nullptr, NM, 3 * NC, NC);

    // 2) causal attention -> g_att (rounded)
    attn_tc<<<dim3(NT / 64, NBH), 128, ATTN_SMEM>>>();

    // 3) out = g_att @ Wproj
    gemm_tc<0><<<dim3(NC / BN, NM / BM), 128, GEMM_SMEM>>>(
        (const float*)patt, (const float*)pwproj, out, NM, NC, NC);
}